// round 2
// baseline (speedup 1.0000x reference)
#include <cuda_runtime.h>
#include <cstdint>
#include <cstddef>

#define BATCH 64
#define T 90
#define O 5
#define D 256
#define H 256
#define EA 4096
#define R 5
#define NB 8
#define NPG 95
#define NTOT (BATCH*NPG)      /* 6080 */
#define JW 1536               /* 5*256 relation cols + 256 root cols */
#define XWC 1280              /* relation part of xW */

// ---------------- device scratch (no allocations allowed) ----------------
__device__ float g_W[D*JW];                         // [d][j]  1.5 MB
__device__ float g_xW[(size_t)NTOT*XWC];            // [node][r*256+h]  31 MB
__device__ float g_P[(size_t)BATCH*T*T];            // [b][t][s] softmax probs, 2 MB
__device__ int   g_off[BATCH*(T+1)];                // CSR offsets per graph
__device__ unsigned short g_eid[BATCH*EA];          // dst-sorted edge ids

// ---------------- K1: W[r] = comp @ bases, plus root, concatenated -------
__global__ void k_buildW(const float* __restrict__ bases,
                         const float* __restrict__ comp,
                         const float* __restrict__ root) {
    int idx = blockIdx.x*256 + threadIdx.x;     // 0 .. D*JW-1
    int d = idx / JW, j = idx - d*JW;
    float v;
    if (j < XWC) {
        int r = j >> 8, h = j & 255;
        float s = 0.f;
        #pragma unroll
        for (int n = 0; n < NB; n++)
            s += comp[r*NB + n] * bases[((size_t)n*D + d)*H + h];
        v = s;
    } else {
        v = root[d*H + (j - XWC)];
    }
    g_W[(size_t)d*JW + j] = v;
}

// ---------------- K3: per-graph attention: scale = M[b] @ Ws^T, colwise softmax
// smem: sM[96][257] + sW[96][257] + sS[90][91]  = 230,136 B (<= 227 KB opt-in)
__global__ void k_attn(const float* __restrict__ M, const float* __restrict__ Ws) {
    extern __shared__ float sm[];
    float* sM = sm;                 // 96*257
    float* sW = sm + 96*257;        // 96*257
    float* sS = sm + 2*96*257;      // 90*91
    int b = blockIdx.x, tid = threadIdx.x;

    // load M[b] (90x256) and Ws (90x256), padded stride 257 (bank-conflict free)
    for (int q = tid; q < T*(D/4); q += 256) {
        int m = q >> 6, d4 = (q & 63) << 2;
        float4 v = *(const float4*)(M + ((size_t)b*T + m)*D + d4);
        float* p = sM + m*257 + d4;
        p[0]=v.x; p[1]=v.y; p[2]=v.z; p[3]=v.w;
    }
    for (int q = tid; q < T*(D/4); q += 256) {
        int m = q >> 6, d4 = (q & 63) << 2;
        float4 v = *(const float4*)(Ws + (size_t)m*D + d4);
        float* p = sW + m*257 + d4;
        p[0]=v.x; p[1]=v.y; p[2]=v.z; p[3]=v.w;
    }
    // zero pad rows 90..95
    for (int q = tid; q < 6*257; q += 256) { sM[90*257 + q] = 0.f; sW[90*257 + q] = 0.f; }
    __syncthreads();

    // 16x16 threads, 6x6 register tile each -> 96x96 (guarded to 90x90)
    int tx = tid & 15, ty = tid >> 4;
    int m0 = ty*6, s0 = tx*6;
    float acc[6][6];
    #pragma unroll
    for (int i = 0; i < 6; i++)
        #pragma unroll
        for (int j = 0; j < 6; j++) acc[i][j] = 0.f;

    for (int k = 0; k < D; k++) {
        float a[6], bb[6];
        #pragma unroll
        for (int i = 0; i < 6; i++) { a[i] = sM[(m0+i)*257 + k]; bb[i] = sW[(s0+i)*257 + k]; }
        #pragma unroll
        for (int i = 0; i < 6; i++)
            #pragma unroll
            for (int j = 0; j < 6; j++) acc[i][j] += a[i]*bb[j];
    }
    #pragma unroll
    for (int i = 0; i < 6; i++)
        #pragma unroll
        for (int j = 0; j < 6; j++) {
            int m = m0+i, s = s0+j;
            if (m < T && s < T) sS[m*91 + s] = acc[i][j];
        }
    __syncthreads();

    // softmax over t for each column s; write P[b][t][s]
    if (tid < T) {
        int s = tid;
        float mx = -1e30f;
        for (int t = 0; t < T; t++) mx = fmaxf(mx, sS[t*91 + s]);
        float den = 0.f;
        for (int t = 0; t < T; t++) den += __expf(sS[t*91 + s] - mx);
        float inv = 1.f/den;
        for (int t = 0; t < T; t++)
            g_P[((size_t)b*T + t)*T + s] = __expf(sS[t*91 + s] - mx) * inv;
    }
}

// ---------------- K4: per-graph CSR (bucket attention edges by dst) ------
__global__ void k_csr(const int* __restrict__ edge_dst) {
    __shared__ int cnt[T], offs[T+1], cur[T];
    int b = blockIdx.x, tid = threadIdx.x;   // 128 threads
    if (tid < T) cnt[tid] = 0;
    __syncthreads();
    for (int e = tid; e < EA; e += 128) atomicAdd(&cnt[edge_dst[(size_t)b*EA + e]], 1);
    __syncthreads();
    if (tid == 0) {
        int a = 0;
        for (int i = 0; i < T; i++) { offs[i] = a; a += cnt[i]; }
        offs[T] = a;
    }
    __syncthreads();
    if (tid < T)  cur[tid] = offs[tid];
    if (tid <= T) g_off[b*(T+1) + tid] = offs[tid];
    __syncthreads();
    for (int e = tid; e < EA; e += 128) {
        int dv = edge_dst[(size_t)b*EA + e];
        int pos = atomicAdd(&cur[dv], 1);
        g_eid[(size_t)b*EA + pos] = (unsigned short)e;
    }
}

// ---------------- K2: fused GEMM  xW|base = x @ [W_0..W_4 | root] --------
// 128x128 tile, BK=16, 256 threads, 8x8/thread (as 2x2 of 4x4 for coalescing)
__global__ void k_gemm(const float* __restrict__ x,
                       const float* __restrict__ bias,
                       float* __restrict__ out) {
    __shared__ float As[16][132];
    __shared__ float Bs[16][132];
    int tid = threadIdx.x;
    int row0 = blockIdx.x*128, col0 = blockIdx.y*128;
    int tx = tid & 15, ty = tid >> 4;
    float acc[8][8];
    #pragma unroll
    for (int i = 0; i < 8; i++)
        #pragma unroll
        for (int j = 0; j < 8; j++) acc[i][j] = 0.f;

    for (int k0 = 0; k0 < D; k0 += 16) {
        #pragma unroll
        for (int i = 0; i < 2; i++) {          // A tile 128x16, transposed store
            int q = tid + i*256;
            int r = q >> 2, kk = (q & 3) << 2;
            int row = row0 + r;
            float4 v = make_float4(0.f,0.f,0.f,0.f);
            if (row < NTOT) v = *(const float4*)(x + (size_t)row*D + k0 + kk);
            As[kk+0][r] = v.x; As[kk+1][r] = v.y; As[kk+2][r] = v.z; As[kk+3][r] = v.w;
        }
        #pragma unroll
        for (int i = 0; i < 2; i++) {          // B tile 16x128
            int q = tid + i*256;
            int kk = q >> 5, c = (q & 31) << 2;
            *(float4*)&Bs[kk][c] = *(const float4*)(g_W + (size_t)(k0+kk)*JW + col0 + c);
        }
        __syncthreads();
        #pragma unroll
        for (int kk = 0; kk < 16; kk++) {
            float a[8], bb[8];
            #pragma unroll
            for (int p = 0; p < 2; p++) {
                float4 v = *(float4*)&As[kk][ty*4 + p*64];
                a[p*4+0]=v.x; a[p*4+1]=v.y; a[p*4+2]=v.z; a[p*4+3]=v.w;
                float4 u = *(float4*)&Bs[kk][tx*4 + p*64];
                bb[p*4+0]=u.x; bb[p*4+1]=u.y; bb[p*4+2]=u.z; bb[p*4+3]=u.w;
            }
            #pragma unroll
            for (int mi = 0; mi < 8; mi++)
                #pragma unroll
                for (int ni = 0; ni < 8; ni++) acc[mi][ni] += a[mi]*bb[ni];
        }
        __syncthreads();
    }
    // epilogue: relation cols -> g_xW ; root cols -> d_out (+bias)
    #pragma unroll
    for (int p = 0; p < 2; p++)
        #pragma unroll
        for (int mi = 0; mi < 4; mi++) {
            int row = row0 + ty*4 + p*64 + mi;
            if (row >= NTOT) continue;
            #pragma unroll
            for (int q = 0; q < 2; q++) {
                int col = col0 + tx*4 + q*64;
                float4 v = make_float4(acc[p*4+mi][q*4+0], acc[p*4+mi][q*4+1],
                                       acc[p*4+mi][q*4+2], acc[p*4+mi][q*4+3]);
                if (col < XWC) {
                    *(float4*)(g_xW + (size_t)row*XWC + col) = v;
                } else {
                    int h = col - XWC;
                    v.x += bias[h+0]; v.y += bias[h+1]; v.z += bias[h+2]; v.w += bias[h+3];
                    *(float4*)(out + (size_t)row*H + h) = v;
                }
            }
        }
}

// ---------------- K5: warp-per-node aggregation (no atomics) -------------
__global__ void k_agg(const int* __restrict__ edge_src,
                      const int* __restrict__ edge_type,
                      const float* __restrict__ node_att,
                      float* __restrict__ out) {
    int w = (blockIdx.x*blockDim.x + threadIdx.x) >> 5;   // node id = b*NPG+dst
    int l = threadIdx.x & 31;
    if (w >= NTOT) return;
    int b = w / NPG, dn = w - b*NPG;
    float4* out4 = (float4*)out;
    float4 acc0 = out4[(size_t)w*64 + l];         // base = x@root + bias
    float4 acc1 = out4[(size_t)w*64 + 32 + l];

    if (dn < T) {
        int i0 = g_off[b*(T+1) + dn];
        int i1 = g_off[b*(T+1) + dn + 1];
        const float* Pd = g_P + ((size_t)b*T + dn)*T;
        const int* esrc = edge_src + (size_t)b*EA;
        const int* etyp = edge_type + (size_t)b*EA;
        const unsigned short* eid = g_eid + (size_t)b*EA;
        for (int i = i0; i < i1; i++) {
            int e   = eid[i];
            int src = esrc[e];
            int ty  = etyp[e];
            float norm = Pd[src];
            const float4* p = (const float4*)(g_xW + ((size_t)(b*NPG + src)*XWC + ty*H));
            float4 v0 = p[l], v1 = p[32 + l];
            acc0.x += norm*v0.x; acc0.y += norm*v0.y; acc0.z += norm*v0.z; acc0.w += norm*v0.w;
            acc1.x += norm*v1.x; acc1.y += norm*v1.y; acc1.z += norm*v1.z; acc1.w += norm*v1.w;
        }
    } else {
        int o = dn - T;   // user node: edges i -> T+o, type R-1, norm = node_att[b,i,o]
        const float* na = node_att + (size_t)b*T*O + o;
        #pragma unroll 2
        for (int i = 0; i < T; i++) {
            float norm = na[i*O];
            const float4* p = (const float4*)(g_xW + ((size_t)(b*NPG + i)*XWC + (R-1)*H));
            float4 v0 = p[l], v1 = p[32 + l];
            acc0.x += norm*v0.x; acc0.y += norm*v0.y; acc0.z += norm*v0.z; acc0.w += norm*v0.w;
            acc1.x += norm*v1.x; acc1.y += norm*v1.y; acc1.z += norm*v1.z; acc1.w += norm*v1.w;
        }
    }
    out4[(size_t)w*64 + l] = acc0;
    out4[(size_t)w*64 + 32 + l] = acc1;
}

// ---------------- launch -------------------------------------------------
extern "C" void kernel_launch(void* const* d_in, const int* in_sizes, int n_in,
                              void* d_out, int out_size) {
    const float* M     = (const float*)d_in[0];
    const float* x     = (const float*)d_in[1];
    const float* natt  = (const float*)d_in[2];
    const float* Ws    = (const float*)d_in[3];
    const float* bases = (const float*)d_in[4];
    const float* comp  = (const float*)d_in[5];
    const float* root  = (const float*)d_in[6];
    const float* bias  = (const float*)d_in[7];
    const int* esrc    = (const int*)d_in[8];
    const int* edst    = (const int*)d_in[9];
    const int* etyp    = (const int*)d_in[10];
    float* out = (float*)d_out;

    const int SMEM_ATTN = (2*96*257 + 90*91)*(int)sizeof(float);  // 230,136 B
    cudaFuncSetAttribute(k_attn, cudaFuncAttributeMaxDynamicSharedMemorySize, SMEM_ATTN);

    k_buildW<<<(D*JW)/256, 256>>>(bases, comp, root);
    k_attn<<<BATCH, 256, SMEM_ATTN>>>(M, Ws);
    k_csr<<<BATCH, 128>>>(edst);
    k_gemm<<<dim3((NTOT+127)/128, JW/128), 256>>>(x, bias, out);
    k_agg<<<(NTOT*32 + 127)/128, 128>>>(esrc, etyp, natt, out);
}

// round 5
// speedup vs baseline: 1.2521x; 1.2521x over previous
#include <cuda_runtime.h>
#include <cuda_bf16.h>
#include <cstdint>
#include <cstddef>

#define BATCH 64
#define T 90
#define O 5
#define D 256
#define H 256
#define EA 4096
#define R 5
#define NB 8
#define NPG 95
#define NTOT (BATCH*NPG)      /* 6080 */
#define JW 1536               /* 5*256 relation cols + 256 root cols */
#define XWC 1280              /* relation part of xW */
#define MROWS 6144            /* NTOT padded to 48*128 */
#define KP 768                /* split-K: [hi | lo | hi] */

// ---------------- device scratch ----------------
__device__ __align__(128) float g_xW[(size_t)NTOT*XWC];           // 31 MB
__device__ __align__(128) float g_P[(size_t)BATCH*T*T];           // softmax probs
__device__ __align__(128) int   g_off[BATCH*(T+1)];
__device__ __align__(128) unsigned short g_eid[BATCH*EA];
__device__ __align__(128) __nv_bfloat16 g_Abf[(size_t)MROWS*KP];  // 9.4 MB  [row][k]
__device__ __align__(128) __nv_bfloat16 g_Bbf[(size_t)JW*KP];     // 2.4 MB  [n][k]

// ---------------- PTX helpers (baseline-PTX only: sm_80-class) ----------------
__device__ __forceinline__ uint32_t smem_u32(const void* p) {
    uint32_t a;
    asm("{ .reg .u64 t; cvta.to.shared.u64 t, %1; cvt.u32.u64 %0, t; }" : "=r"(a) : "l"(p));
    return a;
}
#define CP16(dst,src)    asm volatile("cp.async.cg.shared.global [%0], [%1], 16;"::"r"(dst),"l"(src):"memory")
#define CP_COMMIT()      asm volatile("cp.async.commit_group;":::"memory")
#define CP_WAIT(n)       asm volatile("cp.async.wait_group %0;"::"n"(n):"memory")
#define LDSM4(r0,r1,r2,r3,addr) \
    asm volatile("ldmatrix.sync.aligned.m8n8.x4.shared.b16 {%0,%1,%2,%3}, [%4];" \
                 : "=r"(r0),"=r"(r1),"=r"(r2),"=r"(r3) : "r"(addr))
#define MMA16816(c, a, b0, b1) \
    asm volatile("mma.sync.aligned.m16n8k16.row.col.f32.bf16.bf16.f32 " \
                 "{%0,%1,%2,%3},{%4,%5,%6,%7},{%8,%9},{%0,%1,%2,%3};" \
                 : "+f"((c)[0]),"+f"((c)[1]),"+f"((c)[2]),"+f"((c)[3]) \
                 : "r"((a)[0]),"r"((a)[1]),"r"((a)[2]),"r"((a)[3]),"r"(b0),"r"(b1))

// ---------------- K1: B' = split([comp@bases | root]) into [hi|hi|lo] ----
__global__ void k_buildB(const float* __restrict__ bases,
                         const float* __restrict__ comp,
                         const float* __restrict__ root) {
    int idx = blockIdx.x*256 + threadIdx.x;     // 0 .. D*JW-1
    int d = idx / JW, j = idx - d*JW;
    float v;
    if (j < XWC) {
        int r = j >> 8, h = j & 255;
        float s = 0.f;
        #pragma unroll
        for (int n = 0; n < NB; n++)
            s += comp[r*NB + n] * bases[((size_t)n*D + d)*H + h];
        v = s;
    } else {
        v = root[d*H + (j - XWC)];
    }
    __nv_bfloat16 hi = __float2bfloat16(v);
    __nv_bfloat16 lo = __float2bfloat16(v - __bfloat162float(hi));
    g_Bbf[(size_t)j*KP + d]       = hi;
    g_Bbf[(size_t)j*KP + 256 + d] = hi;
    g_Bbf[(size_t)j*KP + 512 + d] = lo;
}

// ---------------- K1b: A' = split(x) into [hi|lo|hi] ----------------------
__global__ void k_convA(const float* __restrict__ x) {
    int idx = blockIdx.x*256 + threadIdx.x;   // 0 .. MROWS*256-1
    int row = idx >> 8, col = idx & 255;
    float v = (row < NTOT) ? x[(size_t)row*D + col] : 0.f;
    __nv_bfloat16 hi = __float2bfloat16(v);
    __nv_bfloat16 lo = __float2bfloat16(v - __bfloat162float(hi));
    g_Abf[(size_t)row*KP + col]       = hi;
    g_Abf[(size_t)row*KP + 256 + col] = lo;
    g_Abf[(size_t)row*KP + 512 + col] = hi;
}

// ---------------- K3: attention ------------------------------------------
__global__ void k_attn(const float* __restrict__ M, const float* __restrict__ Ws) {
    extern __shared__ float sm[];
    float* sM = sm;
    float* sW = sm + 96*257;
    float* sS = sm + 2*96*257;
    int b = blockIdx.x, tid = threadIdx.x;
    for (int q = tid; q < T*(D/4); q += 256) {
        int m = q >> 6, d4 = (q & 63) << 2;
        float4 v = *(const float4*)(M + ((size_t)b*T + m)*D + d4);
        float* p = sM + m*257 + d4;
        p[0]=v.x; p[1]=v.y; p[2]=v.z; p[3]=v.w;
    }
    for (int q = tid; q < T*(D/4); q += 256) {
        int m = q >> 6, d4 = (q & 63) << 2;
        float4 v = *(const float4*)(Ws + (size_t)m*D + d4);
        float* p = sW + m*257 + d4;
        p[0]=v.x; p[1]=v.y; p[2]=v.z; p[3]=v.w;
    }
    for (int q = tid; q < 6*257; q += 256) { sM[90*257 + q] = 0.f; sW[90*257 + q] = 0.f; }
    __syncthreads();
    int tx = tid & 15, ty = tid >> 4;
    int m0 = ty*6, s0 = tx*6;
    float acc[6][6];
    #pragma unroll
    for (int i = 0; i < 6; i++)
        #pragma unroll
        for (int j = 0; j < 6; j++) acc[i][j] = 0.f;
    for (int k = 0; k < D; k++) {
        float a[6], bb[6];
        #pragma unroll
        for (int i = 0; i < 6; i++) { a[i] = sM[(m0+i)*257 + k]; bb[i] = sW[(s0+i)*257 + k]; }
        #pragma unroll
        for (int i = 0; i < 6; i++)
            #pragma unroll
            for (int j = 0; j < 6; j++) acc[i][j] += a[i]*bb[j];
    }
    #pragma unroll
    for (int i = 0; i < 6; i++)
        #pragma unroll
        for (int j = 0; j < 6; j++) {
            int m = m0+i, s = s0+j;
            if (m < T && s < T) sS[m*91 + s] = acc[i][j];
        }
    __syncthreads();
    if (tid < T) {
        int s = tid;
        float mx = -1e30f;
        for (int t = 0; t < T; t++) mx = fmaxf(mx, sS[t*91 + s]);
        float den = 0.f;
        for (int t = 0; t < T; t++) den += __expf(sS[t*91 + s] - mx);
        float inv = 1.f/den;
        for (int t = 0; t < T; t++)
            g_P[((size_t)b*T + t)*T + s] = __expf(sS[t*91 + s] - mx) * inv;
    }
}

// ---------------- K4: CSR -------------------------------------------------
__global__ void k_csr(const int* __restrict__ edge_dst) {
    __shared__ int cnt[T], offs[T+1], cur[T];
    int b = blockIdx.x, tid = threadIdx.x;
    if (tid < T) cnt[tid] = 0;
    __syncthreads();
    for (int e = tid; e < EA; e += 128) atomicAdd(&cnt[edge_dst[(size_t)b*EA + e]], 1);
    __syncthreads();
    if (tid == 0) {
        int a = 0;
        for (int i = 0; i < T; i++) { offs[i] = a; a += cnt[i]; }
        offs[T] = a;
    }
    __syncthreads();
    if (tid < T)  cur[tid] = offs[tid];
    if (tid <= T) g_off[b*(T+1) + tid] = offs[tid];
    __syncthreads();
    for (int e = tid; e < EA; e += 128) {
        int dv = edge_dst[(size_t)b*EA + e];
        int pos = atomicAdd(&cur[dv], 1);
        g_eid[(size_t)b*EA + pos] = (unsigned short)e;
    }
}

// ---------------- K2: mma.sync bf16-split GEMM ----------------------------
// C[6144,1536] = A'[6144,768] @ B'[1536,768]^T
// 128x128 tile, BK=32, 8 warps (4x2), warp tile 32x64, double-buffered cp.async
#define SPITCH 40            /* smem row pitch in halves (80 B, conflict-free) */
#define STAGE_HALVES (128*SPITCH)

__global__ void __launch_bounds__(256, 2) k_mm(const float* __restrict__ bias,
                                               float* __restrict__ out) {
    __shared__ __nv_bfloat16 sA[2][STAGE_HALVES];
    __shared__ __nv_bfloat16 sB[2][STAGE_HALVES];
    int tid = threadIdx.x, lane = tid & 31, wid = tid >> 5;
    int warpM = wid & 3, warpN = wid >> 2;
    int row0 = blockIdx.x * 128;
    int colTile = blockIdx.y, col0 = colTile * 128;

    uint32_t sbA = smem_u32(sA), sbB = smem_u32(sB);

    float c[2][8][4];
    #pragma unroll
    for (int mt = 0; mt < 2; mt++)
        #pragma unroll
        for (int nt = 0; nt < 8; nt++)
            #pragma unroll
            for (int q = 0; q < 4; q++) c[mt][nt][q] = 0.f;

    // per-thread load slots: 512 16B chunks per tile per matrix
    int lrow = tid >> 2, lseg = tid & 3;     // +256 -> rows 64..127
    const __nv_bfloat16* gA = g_Abf + (size_t)(row0 + lrow)*KP + lseg*8;
    const __nv_bfloat16* gB = g_Bbf + (size_t)(col0 + lrow)*KP + lseg*8;
    uint32_t dA = sbA + (lrow*SPITCH + lseg*8)*2;
    uint32_t dB = sbB + (lrow*SPITCH + lseg*8)*2;
    const int rstep = 64;  // +256 threads -> +64 rows

    // prologue: stage 0 (kt=0)
    {
        CP16(dA,                        (const char*)(gA));
        CP16(dA + rstep*SPITCH*2,       (const char*)(gA + (size_t)rstep*KP));
        CP16(dB,                        (const char*)(gB));
        CP16(dB + rstep*SPITCH*2,       (const char*)(gB + (size_t)rstep*KP));
        CP_COMMIT();
    }

    // ldmatrix address precompute (within-stage offsets)
    int aRow = warpM*32 + ((lane>>3)&1)*8 + (lane&7);     // + mt*16
    int aCol = ((lane>>4)&1)*8;                           // + ks*16
    int bRow = warpN*64 + ((lane>>4)&1)*8 + (lane&7);     // + ntp*16
    int bCol = ((lane>>3)&1)*8;                           // + ks*16
    uint32_t aAddr0 = sbA + (aRow*SPITCH + aCol)*2;
    uint32_t bAddr0 = sbB + (bRow*SPITCH + bCol)*2;

    for (int kt = 0; kt < 24; kt++) {
        int s = kt & 1;
        if (kt + 1 < 24) {
            int so = s ^ 1;
            size_t go = (size_t)(kt+1)*32;
            uint32_t soff = so * STAGE_HALVES * 2;
            CP16(dA + soff,                  (const char*)(gA + go));
            CP16(dA + soff + rstep*SPITCH*2, (const char*)(gA + go + (size_t)rstep*KP));
            CP16(dB + soff,                  (const char*)(gB + go));
            CP16(dB + soff + rstep*SPITCH*2, (const char*)(gB + go + (size_t)rstep*KP));
            CP_COMMIT();
            CP_WAIT(1);
        } else {
            CP_WAIT(0);
        }
        __syncthreads();

        uint32_t sa = aAddr0 + s * STAGE_HALVES * 2;
        uint32_t sb2 = bAddr0 + s * STAGE_HALVES * 2;
        #pragma unroll
        for (int ks = 0; ks < 2; ks++) {
            uint32_t a[2][4];
            LDSM4(a[0][0],a[0][1],a[0][2],a[0][3], sa + ks*32);           // m tile 0
            LDSM4(a[1][0],a[1][1],a[1][2],a[1][3], sa + ks*32 + 16*SPITCH*2); // m tile 1
            uint32_t b[8][2];
            #pragma unroll
            for (int ntp = 0; ntp < 4; ntp++) {
                uint32_t r0,r1,r2,r3;
                LDSM4(r0,r1,r2,r3, sb2 + ks*32 + ntp*16*SPITCH*2);
                b[ntp*2+0][0]=r0; b[ntp*2+0][1]=r1;
                b[ntp*2+1][0]=r2; b[ntp*2+1][1]=r3;
            }
            #pragma unroll
            for (int mt = 0; mt < 2; mt++)
                #pragma unroll
                for (int nt = 0; nt < 8; nt++)
                    MMA16816(c[mt][nt], a[mt], b[nt][0], b[nt][1]);
        }
        __syncthreads();
    }

    // epilogue
    int gr = lane >> 2, ci = lane & 3;
    #pragma unroll
    for (int mt = 0; mt < 2; mt++) {
        int r0w = row0 + warpM*32 + mt*16 + gr;
        #pragma unroll
        for (int nt = 0; nt < 8; nt++) {
            int col = col0 + warpN*64 + nt*8 + ci*2;
            if (colTile < 10) {
                if (r0w < NTOT)
                    *(float2*)(g_xW + (size_t)r0w*XWC + col) = make_float2(c[mt][nt][0], c[mt][nt][1]);
                if (r0w + 8 < NTOT)
                    *(float2*)(g_xW + (size_t)(r0w+8)*XWC + col) = make_float2(c[mt][nt][2], c[mt][nt][3]);
            } else {
                int h = col - XWC;
                float b0 = bias[h], b1 = bias[h+1];
                if (r0w < NTOT)
                    *(float2*)(out + (size_t)r0w*H + h) = make_float2(c[mt][nt][0] + b0, c[mt][nt][1] + b1);
                if (r0w + 8 < NTOT)
                    *(float2*)(out + (size_t)(r0w+8)*H + h) = make_float2(c[mt][nt][2] + b0, c[mt][nt][3] + b1);
            }
        }
    }
}

// ---------------- K5: warp-per-node aggregation ---------------------------
__global__ void k_agg(const int* __restrict__ edge_src,
                      const int* __restrict__ edge_type,
                      const float* __restrict__ node_att,
                      float* __restrict__ out) {
    int w = (blockIdx.x*blockDim.x + threadIdx.x) >> 5;
    int l = threadIdx.x & 31;
    if (w >= NTOT) return;
    int b = w / NPG, dn = w - b*NPG;
    float4* out4 = (float4*)out;
    float4 acc0 = out4[(size_t)w*64 + l];
    float4 acc1 = out4[(size_t)w*64 + 32 + l];

    if (dn < T) {
        int i0 = g_off[b*(T+1) + dn];
        int i1 = g_off[b*(T+1) + dn + 1];
        const float* Pd = g_P + ((size_t)b*T + dn)*T;
        const int* esrc = edge_src + (size_t)b*EA;
        const int* etyp = edge_type + (size_t)b*EA;
        const unsigned short* eid = g_eid + (size_t)b*EA;
        for (int i = i0; i < i1; i++) {
            int e   = eid[i];
            int src = esrc[e];
            int ty  = etyp[e];
            float norm = Pd[src];
            const float4* p = (const float4*)(g_xW + ((size_t)(b*NPG + src)*XWC + ty*H));
            float4 v0 = p[l], v1 = p[32 + l];
            acc0.x += norm*v0.x; acc0.y += norm*v0.y; acc0.z += norm*v0.z; acc0.w += norm*v0.w;
            acc1.x += norm*v1.x; acc1.y += norm*v1.y; acc1.z += norm*v1.z; acc1.w += norm*v1.w;
        }
    } else {
        int o = dn - T;
        const float* na = node_att + (size_t)b*T*O + o;
        #pragma unroll 2
        for (int i = 0; i < T; i++) {
            float norm = na[i*O];
            const float4* p = (const float4*)(g_xW + ((size_t)(b*NPG + i)*XWC + (R-1)*H));
            float4 v0 = p[l], v1 = p[32 + l];
            acc0.x += norm*v0.x; acc0.y += norm*v0.y; acc0.z += norm*v0.z; acc0.w += norm*v0.w;
            acc1.x += norm*v1.x; acc1.y += norm*v1.y; acc1.z += norm*v1.z; acc1.w += norm*v1.w;
        }
    }
    out4[(size_t)w*64 + l] = acc0;
    out4[(size_t)w*64 + 32 + l] = acc1;
}

// ---------------- launch -------------------------------------------------
extern "C" void kernel_launch(void* const* d_in, const int* in_sizes, int n_in,
                              void* d_out, int out_size) {
    const float* M     = (const float*)d_in[0];
    const float* x     = (const float*)d_in[1];
    const float* natt  = (const float*)d_in[2];
    const float* Ws    = (const float*)d_in[3];
    const float* bases = (const float*)d_in[4];
    const float* comp  = (const float*)d_in[5];
    const float* root  = (const float*)d_in[6];
    const float* bias  = (const float*)d_in[7];
    const int* esrc    = (const int*)d_in[8];
    const int* edst    = (const int*)d_in[9];
    const int* etyp    = (const int*)d_in[10];
    float* out = (float*)d_out;

    const int SMEM_ATTN = (2*96*257 + 90*91)*(int)sizeof(float);
    cudaFuncSetAttribute(k_attn, cudaFuncAttributeMaxDynamicSharedMemorySize, SMEM_ATTN);

    k_buildB<<<(D*JW)/256, 256>>>(bases, comp, root);
    k_convA<<<(MROWS*256)/256, 256>>>(x);
    k_attn<<<BATCH, 256, SMEM_ATTN>>>(M, Ws);
    k_csr<<<BATCH, 128>>>(edst);
    k_mm<<<dim3(MROWS/128, JW/128), 256>>>(bias, out);
    k_agg<<<(NTOT*32 + 127)/128, 128>>>(esrc, etyp, natt, out);
}

// round 6
// speedup vs baseline: 1.4590x; 1.1652x over previous
#include <cuda_runtime.h>
#include <cuda_bf16.h>
#include <cstdint>
#include <cstddef>

#define BATCH 64
#define T 90
#define O 5
#define D 256
#define H 256
#define EA 4096
#define R 5
#define NB 8
#define NPG 95
#define NTOT (BATCH*NPG)      /* 6080 */
#define JW 1536               /* 5*256 relation cols + 256 root cols */
#define XWC 1280              /* relation part of xW */
#define MROWS 6144            /* NTOT padded to 48*128 */
#define KP 768                /* split-K: [hi | lo | hi] */

// ---------------- device scratch ----------------
__device__ __align__(128) float g_xW[(size_t)NTOT*XWC];           // 31 MB
__device__ __align__(128) float g_P[(size_t)BATCH*T*T];           // softmax probs
__device__ __align__(128) int   g_off[BATCH*(T+1)];
__device__ __align__(128) unsigned short g_eid[BATCH*EA];
__device__ __align__(128) __nv_bfloat16 g_Abf[(size_t)MROWS*KP];  // 9.4 MB  [row][k]
__device__ __align__(128) __nv_bfloat16 g_Bbf[(size_t)JW*KP];     // 2.4 MB  [n][k]

// ---------------- PTX helpers (baseline-PTX only: sm_80-class) ----------------
__device__ __forceinline__ uint32_t smem_u32(const void* p) {
    uint32_t a;
    asm("{ .reg .u64 t; cvta.to.shared.u64 t, %1; cvt.u32.u64 %0, t; }" : "=r"(a) : "l"(p));
    return a;
}
#define CP16(dst,src)    asm volatile("cp.async.cg.shared.global [%0], [%1], 16;"::"r"(dst),"l"(src):"memory")
#define CP_COMMIT()      asm volatile("cp.async.commit_group;":::"memory")
#define CP_WAIT(n)       asm volatile("cp.async.wait_group %0;"::"n"(n):"memory")
#define LDSM4(r0,r1,r2,r3,addr) \
    asm volatile("ldmatrix.sync.aligned.m8n8.x4.shared.b16 {%0,%1,%2,%3}, [%4];" \
                 : "=r"(r0),"=r"(r1),"=r"(r2),"=r"(r3) : "r"(addr))
#define MMA16816(c, a, b0, b1) \
    asm volatile("mma.sync.aligned.m16n8k16.row.col.f32.bf16.bf16.f32 " \
                 "{%0,%1,%2,%3},{%4,%5,%6,%7},{%8,%9},{%0,%1,%2,%3};" \
                 : "+f"((c)[0]),"+f"((c)[1]),"+f"((c)[2]),"+f"((c)[3]) \
                 : "r"((a)[0]),"r"((a)[1]),"r"((a)[2]),"r"((a)[3]),"r"(b0),"r"(b1))

// ---------------- K1: B' = split([comp@bases | root]) into [hi|hi|lo] ----
__global__ void k_buildB(const float* __restrict__ bases,
                         const float* __restrict__ comp,
                         const float* __restrict__ root) {
    int idx = blockIdx.x*256 + threadIdx.x;     // 0 .. D*JW-1
    int d = idx / JW, j = idx - d*JW;
    float v;
    if (j < XWC) {
        int r = j >> 8, h = j & 255;
        float s = 0.f;
        #pragma unroll
        for (int n = 0; n < NB; n++)
            s += comp[r*NB + n] * bases[((size_t)n*D + d)*H + h];
        v = s;
    } else {
        v = root[d*H + (j - XWC)];
    }
    __nv_bfloat16 hi = __float2bfloat16(v);
    __nv_bfloat16 lo = __float2bfloat16(v - __bfloat162float(hi));
    g_Bbf[(size_t)j*KP + d]       = hi;
    g_Bbf[(size_t)j*KP + 256 + d] = hi;
    g_Bbf[(size_t)j*KP + 512 + d] = lo;
}

// ---------------- K1b: A' = split(x) into [hi|lo|hi] ----------------------
__global__ void k_convA(const float* __restrict__ x) {
    int idx = blockIdx.x*256 + threadIdx.x;   // 0 .. MROWS*256-1
    int row = idx >> 8, col = idx & 255;
    float v = (row < NTOT) ? x[(size_t)row*D + col] : 0.f;
    __nv_bfloat16 hi = __float2bfloat16(v);
    __nv_bfloat16 lo = __float2bfloat16(v - __bfloat162float(hi));
    g_Abf[(size_t)row*KP + col]       = hi;
    g_Abf[(size_t)row*KP + 256 + col] = lo;
    g_Abf[(size_t)row*KP + 512 + col] = hi;
}

// ---------------- K3: attention ------------------------------------------
__global__ void k_attn(const float* __restrict__ M, const float* __restrict__ Ws) {
    extern __shared__ float sm[];
    float* sM = sm;
    float* sW = sm + 96*257;
    float* sS = sm + 2*96*257;
    int b = blockIdx.x, tid = threadIdx.x;
    for (int q = tid; q < T*(D/4); q += 256) {
        int m = q >> 6, d4 = (q & 63) << 2;
        float4 v = *(const float4*)(M + ((size_t)b*T + m)*D + d4);
        float* p = sM + m*257 + d4;
        p[0]=v.x; p[1]=v.y; p[2]=v.z; p[3]=v.w;
    }
    for (int q = tid; q < T*(D/4); q += 256) {
        int m = q >> 6, d4 = (q & 63) << 2;
        float4 v = *(const float4*)(Ws + (size_t)m*D + d4);
        float* p = sW + m*257 + d4;
        p[0]=v.x; p[1]=v.y; p[2]=v.z; p[3]=v.w;
    }
    for (int q = tid; q < 6*257; q += 256) { sM[90*257 + q] = 0.f; sW[90*257 + q] = 0.f; }
    __syncthreads();
    int tx = tid & 15, ty = tid >> 4;
    int m0 = ty*6, s0 = tx*6;
    float acc[6][6];
    #pragma unroll
    for (int i = 0; i < 6; i++)
        #pragma unroll
        for (int j = 0; j < 6; j++) acc[i][j] = 0.f;
    for (int k = 0; k < D; k++) {
        float a[6], bb[6];
        #pragma unroll
        for (int i = 0; i < 6; i++) { a[i] = sM[(m0+i)*257 + k]; bb[i] = sW[(s0+i)*257 + k]; }
        #pragma unroll
        for (int i = 0; i < 6; i++)
            #pragma unroll
            for (int j = 0; j < 6; j++) acc[i][j] += a[i]*bb[j];
    }
    #pragma unroll
    for (int i = 0; i < 6; i++)
        #pragma unroll
        for (int j = 0; j < 6; j++) {
            int m = m0+i, s = s0+j;
            if (m < T && s < T) sS[m*91 + s] = acc[i][j];
        }
    __syncthreads();
    if (tid < T) {
        int s = tid;
        float mx = -1e30f;
        for (int t = 0; t < T; t++) mx = fmaxf(mx, sS[t*91 + s]);
        float den = 0.f;
        for (int t = 0; t < T; t++) den += __expf(sS[t*91 + s] - mx);
        float inv = 1.f/den;
        for (int t = 0; t < T; t++)
            g_P[((size_t)b*T + t)*T + s] = __expf(sS[t*91 + s] - mx) * inv;
    }
}

// ---------------- K4: CSR (512 threads for latency hiding) ----------------
__global__ void k_csr(const int* __restrict__ edge_dst) {
    __shared__ int cnt[T], offs[T+1], cur[T];
    int b = blockIdx.x, tid = threadIdx.x;   // 512 threads
    if (tid < T) cnt[tid] = 0;
    __syncthreads();
    #pragma unroll
    for (int q = 0; q < EA/512; q++) {
        int e = tid + q*512;
        atomicAdd(&cnt[edge_dst[(size_t)b*EA + e]], 1);
    }
    __syncthreads();
    if (tid == 0) {
        int a = 0;
        for (int i = 0; i < T; i++) { offs[i] = a; a += cnt[i]; }
        offs[T] = a;
    }
    __syncthreads();
    if (tid < T)  cur[tid] = offs[tid];
    if (tid <= T) g_off[b*(T+1) + tid] = offs[tid];
    __syncthreads();
    #pragma unroll
    for (int q = 0; q < EA/512; q++) {
        int e = tid + q*512;
        int dv = edge_dst[(size_t)b*EA + e];
        int pos = atomicAdd(&cur[dv], 1);
        g_eid[(size_t)b*EA + pos] = (unsigned short)e;
    }
}

// ---------------- K2: mma.sync bf16-split GEMM ----------------------------
// C[6144,1536] = A'[6144,768] @ B'[1536,768]^T
// 128x128 tile, BK=32, 8 warps (4x2), warp tile 32x64, double-buffered cp.async
#define SPITCH 40            /* smem row pitch in halves (80 B, conflict-free) */
#define STAGE_HALVES (128*SPITCH)

__global__ void __launch_bounds__(256, 2) k_mm(const float* __restrict__ bias,
                                               float* __restrict__ out) {
    __shared__ __nv_bfloat16 sA[2][STAGE_HALVES];
    __shared__ __nv_bfloat16 sB[2][STAGE_HALVES];
    int tid = threadIdx.x, lane = tid & 31, wid = tid >> 5;
    int warpM = wid & 3, warpN = wid >> 2;
    int row0 = blockIdx.x * 128;
    int colTile = blockIdx.y, col0 = colTile * 128;

    uint32_t sbA = smem_u32(sA), sbB = smem_u32(sB);

    float c[2][8][4];
    #pragma unroll
    for (int mt = 0; mt < 2; mt++)
        #pragma unroll
        for (int nt = 0; nt < 8; nt++)
            #pragma unroll
            for (int q = 0; q < 4; q++) c[mt][nt][q] = 0.f;

    // per-thread load slots: 512 16B chunks per tile per matrix
    int lrow = tid >> 2, lseg = tid & 3;     // +256 -> rows 64..127
    const __nv_bfloat16* gA = g_Abf + (size_t)(row0 + lrow)*KP + lseg*8;
    const __nv_bfloat16* gB = g_Bbf + (size_t)(col0 + lrow)*KP + lseg*8;
    uint32_t dA = sbA + (lrow*SPITCH + lseg*8)*2;
    uint32_t dB = sbB + (lrow*SPITCH + lseg*8)*2;
    const int rstep = 64;  // +256 threads -> +64 rows

    // prologue: stage 0 (kt=0)
    {
        CP16(dA,                        (const char*)(gA));
        CP16(dA + rstep*SPITCH*2,       (const char*)(gA + (size_t)rstep*KP));
        CP16(dB,                        (const char*)(gB));
        CP16(dB + rstep*SPITCH*2,       (const char*)(gB + (size_t)rstep*KP));
        CP_COMMIT();
    }

    // ldmatrix address precompute (within-stage offsets)
    int aRow = warpM*32 + ((lane>>3)&1)*8 + (lane&7);     // + mt*16
    int aCol = ((lane>>4)&1)*8;                           // + ks*16
    int bRow = warpN*64 + ((lane>>4)&1)*8 + (lane&7);     // + ntp*16
    int bCol = ((lane>>3)&1)*8;                           // + ks*16
    uint32_t aAddr0 = sbA + (aRow*SPITCH + aCol)*2;
    uint32_t bAddr0 = sbB + (bRow*SPITCH + bCol)*2;

    for (int kt = 0; kt < 24; kt++) {
        int s = kt & 1;
        if (kt + 1 < 24) {
            int so = s ^ 1;
            size_t go = (size_t)(kt+1)*32;
            uint32_t soff = so * STAGE_HALVES * 2;
            CP16(dA + soff,                  (const char*)(gA + go));
            CP16(dA + soff + rstep*SPITCH*2, (const char*)(gA + go + (size_t)rstep*KP));
            CP16(dB + soff,                  (const char*)(gB + go));
            CP16(dB + soff + rstep*SPITCH*2, (const char*)(gB + go + (size_t)rstep*KP));
            CP_COMMIT();
            CP_WAIT(1);
        } else {
            CP_WAIT(0);
        }
        __syncthreads();

        uint32_t sa = aAddr0 + s * STAGE_HALVES * 2;
        uint32_t sb2 = bAddr0 + s * STAGE_HALVES * 2;
        #pragma unroll
        for (int ks = 0; ks < 2; ks++) {
            uint32_t a[2][4];
            LDSM4(a[0][0],a[0][1],a[0][2],a[0][3], sa + ks*32);           // m tile 0
            LDSM4(a[1][0],a[1][1],a[1][2],a[1][3], sa + ks*32 + 16*SPITCH*2); // m tile 1
            uint32_t b[8][2];
            #pragma unroll
            for (int ntp = 0; ntp < 4; ntp++) {
                uint32_t r0,r1,r2,r3;
                LDSM4(r0,r1,r2,r3, sb2 + ks*32 + ntp*16*SPITCH*2);
                b[ntp*2+0][0]=r0; b[ntp*2+0][1]=r1;
                b[ntp*2+1][0]=r2; b[ntp*2+1][1]=r3;
            }
            #pragma unroll
            for (int mt = 0; mt < 2; mt++)
                #pragma unroll
                for (int nt = 0; nt < 8; nt++)
                    MMA16816(c[mt][nt], a[mt], b[nt][0], b[nt][1]);
        }
        __syncthreads();
    }

    // epilogue
    int gr = lane >> 2, ci = lane & 3;
    #pragma unroll
    for (int mt = 0; mt < 2; mt++) {
        int r0w = row0 + warpM*32 + mt*16 + gr;
        #pragma unroll
        for (int nt = 0; nt < 8; nt++) {
            int col = col0 + warpN*64 + nt*8 + ci*2;
            if (colTile < 10) {
                if (r0w < NTOT)
                    *(float2*)(g_xW + (size_t)r0w*XWC + col) = make_float2(c[mt][nt][0], c[mt][nt][1]);
                if (r0w + 8 < NTOT)
                    *(float2*)(g_xW + (size_t)(r0w+8)*XWC + col) = make_float2(c[mt][nt][2], c[mt][nt][3]);
            } else {
                int h = col - XWC;
                float b0 = bias[h], b1 = bias[h+1];
                if (r0w < NTOT)
                    *(float2*)(out + (size_t)r0w*H + h) = make_float2(c[mt][nt][0] + b0, c[mt][nt][1] + b1);
                if (r0w + 8 < NTOT)
                    *(float2*)(out + (size_t)(r0w+8)*H + h) = make_float2(c[mt][nt][2] + b0, c[mt][nt][3] + b1);
            }
        }
    }
}

// ---------------- K5: warp-per-node aggregation ---------------------------
__global__ void k_agg(const int* __restrict__ edge_src,
                      const int* __restrict__ edge_type,
                      const float* __restrict__ node_att,
                      float* __restrict__ out) {
    int w = (blockIdx.x*blockDim.x + threadIdx.x) >> 5;
    int l = threadIdx.x & 31;
    if (w >= NTOT) return;
    int b = w / NPG, dn = w - b*NPG;
    float4* out4 = (float4*)out;
    float4 acc0 = out4[(size_t)w*64 + l];
    float4 acc1 = out4[(size_t)w*64 + 32 + l];

    if (dn < T) {
        int i0 = g_off[b*(T+1) + dn];
        int i1 = g_off[b*(T+1) + dn + 1];
        const float* Pd = g_P + ((size_t)b*T + dn)*T;
        const int* esrc = edge_src + (size_t)b*EA;
        const int* etyp = edge_type + (size_t)b*EA;
        const unsigned short* eid = g_eid + (size_t)b*EA;
        for (int i = i0; i < i1; i++) {
            int e   = eid[i];
            int src = esrc[e];
            int ty  = etyp[e];
            float norm = Pd[src];
            const float4* p = (const float4*)(g_xW + ((size_t)(b*NPG + src)*XWC + ty*H));
            float4 v0 = p[l], v1 = p[32 + l];
            acc0.x += norm*v0.x; acc0.y += norm*v0.y; acc0.z += norm*v0.z; acc0.w += norm*v0.w;
            acc1.x += norm*v1.x; acc1.y += norm*v1.y; acc1.z += norm*v1.z; acc1.w += norm*v1.w;
        }
    } else {
        int o = dn - T;
        const float* na = node_att + (size_t)b*T*O + o;
        #pragma unroll 2
        for (int i = 0; i < T; i++) {
            float norm = na[i*O];
            const float4* p = (const float4*)(g_xW + ((size_t)(b*NPG + i)*XWC + (R-1)*H));
            float4 v0 = p[l], v1 = p[32 + l];
            acc0.x += norm*v0.x; acc0.y += norm*v0.y; acc0.z += norm*v0.z; acc0.w += norm*v0.w;
            acc1.x += norm*v1.x; acc1.y += norm*v1.y; acc1.z += norm*v1.z; acc1.w += norm*v1.w;
        }
    }
    out4[(size_t)w*64 + l] = acc0;
    out4[(size_t)w*64 + 32 + l] = acc1;
}

// ---------------- launch (fork-join graph concurrency) --------------------
extern "C" void kernel_launch(void* const* d_in, const int* in_sizes, int n_in,
                              void* d_out, int out_size) {
    const float* M     = (const float*)d_in[0];
    const float* x     = (const float*)d_in[1];
    const float* natt  = (const float*)d_in[2];
    const float* Ws    = (const float*)d_in[3];
    const float* bases = (const float*)d_in[4];
    const float* comp  = (const float*)d_in[5];
    const float* root  = (const float*)d_in[6];
    const float* bias  = (const float*)d_in[7];
    const int* esrc    = (const int*)d_in[8];
    const int* edst    = (const int*)d_in[9];
    const int* etyp    = (const int*)d_in[10];
    float* out = (float*)d_out;

    static cudaStream_t s1 = nullptr, s2 = nullptr;
    static cudaEvent_t  ef = nullptr, e1 = nullptr, e2 = nullptr;
    static bool attr_done = false;
    if (!s1) {
        cudaStreamCreateWithFlags(&s1, cudaStreamNonBlocking);
        cudaStreamCreateWithFlags(&s2, cudaStreamNonBlocking);
        cudaEventCreateWithFlags(&ef, cudaEventDisableTiming);
        cudaEventCreateWithFlags(&e1, cudaEventDisableTiming);
        cudaEventCreateWithFlags(&e2, cudaEventDisableTiming);
    }
    if (!attr_done) {
        const int SMEM_ATTN = (2*96*257 + 90*91)*(int)sizeof(float);
        cudaFuncSetAttribute(k_attn, cudaFuncAttributeMaxDynamicSharedMemorySize, SMEM_ATTN);
        attr_done = true;
    }
    const int SMEM_ATTN = (2*96*257 + 90*91)*(int)sizeof(float);

    // fork from capture-origin (default) stream
    cudaEventRecord(ef, 0);
    cudaStreamWaitEvent(s1, ef, 0);
    cudaStreamWaitEvent(s2, ef, 0);

    // branch A (default stream): buildB -> (join convA) -> mm
    k_buildB<<<(D*JW)/256, 256>>>(bases, comp, root);
    // branch B (s2): convA
    k_convA<<<(MROWS*256)/256, 256, 0, s2>>>(x);
    // branch C (s1): attn -> csr
    k_attn<<<BATCH, 256, SMEM_ATTN, s1>>>(M, Ws);
    k_csr<<<BATCH, 512, 0, s1>>>(edst);

    // join convA into default stream before mm
    cudaEventRecord(e2, s2);
    cudaStreamWaitEvent(0, e2, 0);
    k_mm<<<dim3(MROWS/128, JW/128), 256>>>(bias, out);

    // join attn/csr before agg
    cudaEventRecord(e1, s1);
    cudaStreamWaitEvent(0, e1, 0);
    k_agg<<<(NTOT*32 + 127)/128, 128>>>(esrc, etyp, natt, out);
}

// round 7
// speedup vs baseline: 1.6783x; 1.1503x over previous
#include <cuda_runtime.h>
#include <cuda_fp16.h>
#include <cstdint>
#include <cstddef>

#define BATCH 64
#define T 90
#define O 5
#define D 256
#define H 256
#define EA 4096
#define R 5
#define NB 8
#define NPG 95
#define NTOT (BATCH*NPG)      /* 6080 */
#define JW 1536               /* 5*256 relation cols + 256 root cols */
#define XWC 1280              /* relation part of xW */
#define MROWS 6144            /* NTOT padded to 48*128 */
#define KP 512                /* split-K: A=[hi|lo], B=[hi|hi] (fp16 2-term) */

// ---------------- device scratch ----------------
__device__ __align__(128) __half g_xWh[(size_t)NTOT*XWC];         // 15.6 MB fp16
__device__ __align__(128) float g_P[(size_t)BATCH*T*T];           // softmax probs
__device__ __align__(128) int   g_off[BATCH*(T+1)];
__device__ __align__(128) unsigned short g_eid[BATCH*EA];
__device__ __align__(128) __half g_Abf[(size_t)MROWS*KP];         // 6.3 MB  [row][k]
__device__ __align__(128) __half g_Bbf[(size_t)JW*KP];            // 1.6 MB  [n][k]

// ---------------- PTX helpers (baseline-PTX only: sm_80-class) ----------------
__device__ __forceinline__ uint32_t smem_u32(const void* p) {
    uint32_t a;
    asm("{ .reg .u64 t; cvta.to.shared.u64 t, %1; cvt.u32.u64 %0, t; }" : "=r"(a) : "l"(p));
    return a;
}
#define CP16(dst,src)    asm volatile("cp.async.cg.shared.global [%0], [%1], 16;"::"r"(dst),"l"(src):"memory")
#define CP_COMMIT()      asm volatile("cp.async.commit_group;":::"memory")
#define CP_WAIT(n)       asm volatile("cp.async.wait_group %0;"::"n"(n):"memory")
#define LDSM4(r0,r1,r2,r3,addr) \
    asm volatile("ldmatrix.sync.aligned.m8n8.x4.shared.b16 {%0,%1,%2,%3}, [%4];" \
                 : "=r"(r0),"=r"(r1),"=r"(r2),"=r"(r3) : "r"(addr))
#define MMA16816(c, a, b0, b1) \
    asm volatile("mma.sync.aligned.m16n8k16.row.col.f32.f16.f16.f32 " \
                 "{%0,%1,%2,%3},{%4,%5,%6,%7},{%8,%9},{%0,%1,%2,%3};" \
                 : "+f"((c)[0]),"+f"((c)[1]),"+f"((c)[2]),"+f"((c)[3]) \
                 : "r"((a)[0]),"r"((a)[1]),"r"((a)[2]),"r"((a)[3]),"r"(b0),"r"(b1))

// ---------------- K1: B' = [W_hi | W_hi],  W = [comp@bases | root] --------
__global__ void k_buildB(const float* __restrict__ bases,
                         const float* __restrict__ comp,
                         const float* __restrict__ root) {
    int idx = blockIdx.x*256 + threadIdx.x;     // 0 .. D*JW-1
    int d = idx / JW, j = idx - d*JW;
    float v;
    if (j < XWC) {
        int r = j >> 8, h = j & 255;
        float s = 0.f;
        #pragma unroll
        for (int n = 0; n < NB; n++)
            s += comp[r*NB + n] * bases[((size_t)n*D + d)*H + h];
        v = s;
    } else {
        v = root[d*H + (j - XWC)];
    }
    __half hi = __float2half(v);
    g_Bbf[(size_t)j*KP + d]       = hi;
    g_Bbf[(size_t)j*KP + 256 + d] = hi;
}

// ---------------- K1b: A' = [x_hi | x_lo] (fp16 split of x) --------------
__global__ void k_convA(const float* __restrict__ x) {
    int idx = blockIdx.x*256 + threadIdx.x;   // 0 .. MROWS*256-1
    int row = idx >> 8, col = idx & 255;
    float v = (row < NTOT) ? x[(size_t)row*D + col] : 0.f;
    __half hi = __float2half(v);
    __half lo = __float2half(v - __half2float(hi));
    g_Abf[(size_t)row*KP + col]       = hi;
    g_Abf[(size_t)row*KP + 256 + col] = lo;
}

// ---------------- K3: attention ------------------------------------------
__global__ void k_attn(const float* __restrict__ M, const float* __restrict__ Ws) {
    extern __shared__ float sm[];
    float* sM = sm;
    float* sW = sm + 96*257;
    float* sS = sm + 2*96*257;
    int b = blockIdx.x, tid = threadIdx.x;
    for (int q = tid; q < T*(D/4); q += 256) {
        int m = q >> 6, d4 = (q & 63) << 2;
        float4 v = *(const float4*)(M + ((size_t)b*T + m)*D + d4);
        float* p = sM + m*257 + d4;
        p[0]=v.x; p[1]=v.y; p[2]=v.z; p[3]=v.w;
    }
    for (int q = tid; q < T*(D/4); q += 256) {
        int m = q >> 6, d4 = (q & 63) << 2;
        float4 v = *(const float4*)(Ws + (size_t)m*D + d4);
        float* p = sW + m*257 + d4;
        p[0]=v.x; p[1]=v.y; p[2]=v.z; p[3]=v.w;
    }
    for (int q = tid; q < 6*257; q += 256) { sM[90*257 + q] = 0.f; sW[90*257 + q] = 0.f; }
    __syncthreads();
    int tx = tid & 15, ty = tid >> 4;
    int m0 = ty*6, s0 = tx*6;
    float acc[6][6];
    #pragma unroll
    for (int i = 0; i < 6; i++)
        #pragma unroll
        for (int j = 0; j < 6; j++) acc[i][j] = 0.f;
    for (int k = 0; k < D; k++) {
        float a[6], bb[6];
        #pragma unroll
        for (int i = 0; i < 6; i++) { a[i] = sM[(m0+i)*257 + k]; bb[i] = sW[(s0+i)*257 + k]; }
        #pragma unroll
        for (int i = 0; i < 6; i++)
            #pragma unroll
            for (int j = 0; j < 6; j++) acc[i][j] += a[i]*bb[j];
    }
    #pragma unroll
    for (int i = 0; i < 6; i++)
        #pragma unroll
        for (int j = 0; j < 6; j++) {
            int m = m0+i, s = s0+j;
            if (m < T && s < T) sS[m*91 + s] = acc[i][j];
        }
    __syncthreads();
    if (tid < T) {
        int s = tid;
        float mx = -1e30f;
        for (int t = 0; t < T; t++) mx = fmaxf(mx, sS[t*91 + s]);
        float den = 0.f;
        for (int t = 0; t < T; t++) den += __expf(sS[t*91 + s] - mx);
        float inv = 1.f/den;
        for (int t = 0; t < T; t++)
            g_P[((size_t)b*T + t)*T + s] = __expf(sS[t*91 + s] - mx) * inv;
    }
}

// ---------------- K4: CSR (512 threads for latency hiding) ----------------
__global__ void k_csr(const int* __restrict__ edge_dst) {
    __shared__ int cnt[T], offs[T+1], cur[T];
    int b = blockIdx.x, tid = threadIdx.x;   // 512 threads
    if (tid < T) cnt[tid] = 0;
    __syncthreads();
    #pragma unroll
    for (int q = 0; q < EA/512; q++) {
        int e = tid + q*512;
        atomicAdd(&cnt[edge_dst[(size_t)b*EA + e]], 1);
    }
    __syncthreads();
    if (tid == 0) {
        int a = 0;
        for (int i = 0; i < T; i++) { offs[i] = a; a += cnt[i]; }
        offs[T] = a;
    }
    __syncthreads();
    if (tid < T)  cur[tid] = offs[tid];
    if (tid <= T) g_off[b*(T+1) + tid] = offs[tid];
    __syncthreads();
    #pragma unroll
    for (int q = 0; q < EA/512; q++) {
        int e = tid + q*512;
        int dv = edge_dst[(size_t)b*EA + e];
        int pos = atomicAdd(&cur[dv], 1);
        g_eid[(size_t)b*EA + pos] = (unsigned short)e;
    }
}

// ---------------- K2: mma.sync fp16 2-term split GEMM ---------------------
// C[6144,1536] = A'[6144,512] @ B'[1536,512]^T
// 128x128 tile, BK=32, 8 warps (4x2), warp tile 32x64, double-buffered cp.async
#define SPITCH 40            /* smem row pitch in halves (80 B, conflict-free) */
#define STAGE_HALVES (128*SPITCH)
#define NKT (KP/32)          /* 16 */

__global__ void __launch_bounds__(256, 2) k_mm(const float* __restrict__ bias,
                                               float* __restrict__ out) {
    __shared__ __half sA[2][STAGE_HALVES];
    __shared__ __half sB[2][STAGE_HALVES];
    int tid = threadIdx.x, lane = tid & 31, wid = tid >> 5;
    int warpM = wid & 3, warpN = wid >> 2;
    int row0 = blockIdx.x * 128;
    int colTile = blockIdx.y, col0 = colTile * 128;

    uint32_t sbA = smem_u32(sA), sbB = smem_u32(sB);

    float c[2][8][4];
    #pragma unroll
    for (int mt = 0; mt < 2; mt++)
        #pragma unroll
        for (int nt = 0; nt < 8; nt++)
            #pragma unroll
            for (int q = 0; q < 4; q++) c[mt][nt][q] = 0.f;

    // per-thread load slots: 512 16B chunks per tile per matrix
    int lrow = tid >> 2, lseg = tid & 3;     // +256 -> rows 64..127
    const __half* gA = g_Abf + (size_t)(row0 + lrow)*KP + lseg*8;
    const __half* gB = g_Bbf + (size_t)(col0 + lrow)*KP + lseg*8;
    uint32_t dA = sbA + (lrow*SPITCH + lseg*8)*2;
    uint32_t dB = sbB + (lrow*SPITCH + lseg*8)*2;
    const int rstep = 64;  // +256 threads -> +64 rows

    // prologue: stage 0 (kt=0)
    {
        CP16(dA,                        (const char*)(gA));
        CP16(dA + rstep*SPITCH*2,       (const char*)(gA + (size_t)rstep*KP));
        CP16(dB,                        (const char*)(gB));
        CP16(dB + rstep*SPITCH*2,       (const char*)(gB + (size_t)rstep*KP));
        CP_COMMIT();
    }

    // ldmatrix address precompute (within-stage offsets)
    int aRow = warpM*32 + ((lane>>3)&1)*8 + (lane&7);     // + mt*16
    int aCol = ((lane>>4)&1)*8;                           // + ks*16
    int bRow = warpN*64 + ((lane>>4)&1)*8 + (lane&7);     // + ntp*16
    int bCol = ((lane>>3)&1)*8;                           // + ks*16
    uint32_t aAddr0 = sbA + (aRow*SPITCH + aCol)*2;
    uint32_t bAddr0 = sbB + (bRow*SPITCH + bCol)*2;

    for (int kt = 0; kt < NKT; kt++) {
        int s = kt & 1;
        if (kt + 1 < NKT) {
            int so = s ^ 1;
            size_t go = (size_t)(kt+1)*32;
            uint32_t soff = so * STAGE_HALVES * 2;
            CP16(dA + soff,                  (const char*)(gA + go));
            CP16(dA + soff + rstep*SPITCH*2, (const char*)(gA + go + (size_t)rstep*KP));
            CP16(dB + soff,                  (const char*)(gB + go));
            CP16(dB + soff + rstep*SPITCH*2, (const char*)(gB + go + (size_t)rstep*KP));
            CP_COMMIT();
            CP_WAIT(1);
        } else {
            CP_WAIT(0);
        }
        __syncthreads();

        uint32_t sa = aAddr0 + s * STAGE_HALVES * 2;
        uint32_t sb2 = bAddr0 + s * STAGE_HALVES * 2;
        #pragma unroll
        for (int ks = 0; ks < 2; ks++) {
            uint32_t a[2][4];
            LDSM4(a[0][0],a[0][1],a[0][2],a[0][3], sa + ks*32);           // m tile 0
            LDSM4(a[1][0],a[1][1],a[1][2],a[1][3], sa + ks*32 + 16*SPITCH*2); // m tile 1
            uint32_t b[8][2];
            #pragma unroll
            for (int ntp = 0; ntp < 4; ntp++) {
                uint32_t r0,r1,r2,r3;
                LDSM4(r0,r1,r2,r3, sb2 + ks*32 + ntp*16*SPITCH*2);
                b[ntp*2+0][0]=r0; b[ntp*2+0][1]=r1;
                b[ntp*2+1][0]=r2; b[ntp*2+1][1]=r3;
            }
            #pragma unroll
            for (int mt = 0; mt < 2; mt++)
                #pragma unroll
                for (int nt = 0; nt < 8; nt++)
                    MMA16816(c[mt][nt], a[mt], b[nt][0], b[nt][1]);
        }
        __syncthreads();
    }

    // epilogue: relation cols -> g_xWh (fp16) ; root cols -> out (fp32 + bias)
    int gr = lane >> 2, ci = lane & 3;
    #pragma unroll
    for (int mt = 0; mt < 2; mt++) {
        int r0w = row0 + warpM*32 + mt*16 + gr;
        #pragma unroll
        for (int nt = 0; nt < 8; nt++) {
            int col = col0 + warpN*64 + nt*8 + ci*2;
            if (colTile < 10) {
                if (r0w < NTOT)
                    *(__half2*)(g_xWh + (size_t)r0w*XWC + col) =
                        __floats2half2_rn(c[mt][nt][0], c[mt][nt][1]);
                if (r0w + 8 < NTOT)
                    *(__half2*)(g_xWh + (size_t)(r0w+8)*XWC + col) =
                        __floats2half2_rn(c[mt][nt][2], c[mt][nt][3]);
            } else {
                int h = col - XWC;
                float b0 = bias[h], b1 = bias[h+1];
                if (r0w < NTOT)
                    *(float2*)(out + (size_t)r0w*H + h) = make_float2(c[mt][nt][0] + b0, c[mt][nt][1] + b1);
                if (r0w + 8 < NTOT)
                    *(float2*)(out + (size_t)(r0w+8)*H + h) = make_float2(c[mt][nt][2] + b0, c[mt][nt][3] + b1);
            }
        }
    }
}

// ---------------- K5: warp-per-node aggregation (fp16 gather) -------------
__device__ __forceinline__ void fma8(float* acc, const uint4& v, float norm) {
    const __half2* hv = (const __half2*)&v;
    #pragma unroll
    for (int q = 0; q < 4; q++) {
        float2 f = __half22float2(hv[q]);
        acc[q*2+0] += norm * f.x;
        acc[q*2+1] += norm * f.y;
    }
}

__global__ void k_agg(const int* __restrict__ edge_src,
                      const int* __restrict__ edge_type,
                      const float* __restrict__ node_att,
                      float* __restrict__ out) {
    int w = (blockIdx.x*blockDim.x + threadIdx.x) >> 5;
    int l = threadIdx.x & 31;
    if (w >= NTOT) return;
    int b = w / NPG, dn = w - b*NPG;

    float acc[8];
    {   // base = x@root + bias (written by k_mm)
        float4 v0 = *(const float4*)(out + (size_t)w*H + l*8);
        float4 v1 = *(const float4*)(out + (size_t)w*H + l*8 + 4);
        acc[0]=v0.x; acc[1]=v0.y; acc[2]=v0.z; acc[3]=v0.w;
        acc[4]=v1.x; acc[5]=v1.y; acc[6]=v1.z; acc[7]=v1.w;
    }

    if (dn < T) {
        int i0 = g_off[b*(T+1) + dn];
        int i1 = g_off[b*(T+1) + dn + 1];
        const float* Pd = g_P + ((size_t)b*T + dn)*T;
        const int* esrc = edge_src + (size_t)b*EA;
        const int* etyp = edge_type + (size_t)b*EA;
        const unsigned short* eid = g_eid + (size_t)b*EA;
        for (int i = i0; i < i1; i++) {
            int e   = eid[i];
            int src = esrc[e];
            int ty  = etyp[e];
            float norm = Pd[src];
            const __half* p = g_xWh + ((size_t)(b*NPG + src)*XWC + ty*H);
            uint4 v = *(const uint4*)(p + l*8);
            fma8(acc, v, norm);
        }
    } else {
        int o = dn - T;   // user node: edges i -> T+o, type R-1, norm = node_att[b,i,o]
        const float* na = node_att + (size_t)b*T*O + o;
        #pragma unroll 2
        for (int i = 0; i < T; i++) {
            float norm = na[i*O];
            const __half* p = g_xWh + ((size_t)(b*NPG + i)*XWC + (R-1)*H);
            uint4 v = *(const uint4*)(p + l*8);
            fma8(acc, v, norm);
        }
    }
    *(float4*)(out + (size_t)w*H + l*8)     = make_float4(acc[0], acc[1], acc[2], acc[3]);
    *(float4*)(out + (size_t)w*H + l*8 + 4) = make_float4(acc[4], acc[5], acc[6], acc[7]);
}

// ---------------- launch (fork-join graph concurrency) --------------------
extern "C" void kernel_launch(void* const* d_in, const int* in_sizes, int n_in,
                              void* d_out, int out_size) {
    const float* M     = (const float*)d_in[0];
    const float* x     = (const float*)d_in[1];
    const float* natt  = (const float*)d_in[2];
    const float* Ws    = (const float*)d_in[3];
    const float* bases = (const float*)d_in[4];
    const float* comp  = (const float*)d_in[5];
    const float* root  = (const float*)d_in[6];
    const float* bias  = (const float*)d_in[7];
    const int* esrc    = (const int*)d_in[8];
    const int* edst    = (const int*)d_in[9];
    const int* etyp    = (const int*)d_in[10];
    float* out = (float*)d_out;

    static cudaStream_t s1 = nullptr, s2 = nullptr;
    static cudaEvent_t  ef = nullptr, e1 = nullptr, e2 = nullptr;
    static bool attr_done = false;
    if (!s1) {
        cudaStreamCreateWithFlags(&s1, cudaStreamNonBlocking);
        cudaStreamCreateWithFlags(&s2, cudaStreamNonBlocking);
        cudaEventCreateWithFlags(&ef, cudaEventDisableTiming);
        cudaEventCreateWithFlags(&e1, cudaEventDisableTiming);
        cudaEventCreateWithFlags(&e2, cudaEventDisableTiming);
    }
    if (!attr_done) {
        const int SMEM_ATTN = (2*96*257 + 90*91)*(int)sizeof(float);
        cudaFuncSetAttribute(k_attn, cudaFuncAttributeMaxDynamicSharedMemorySize, SMEM_ATTN);
        attr_done = true;
    }
    const int SMEM_ATTN = (2*96*257 + 90*91)*(int)sizeof(float);

    // fork from capture-origin (default) stream
    cudaEventRecord(ef, 0);
    cudaStreamWaitEvent(s1, ef, 0);
    cudaStreamWaitEvent(s2, ef, 0);

    // branch A (default stream): buildB -> (join convA) -> mm
    k_buildB<<<(D*JW)/256, 256>>>(bases, comp, root);
    // branch B (s2): convA
    k_convA<<<(MROWS*256)/256, 256, 0, s2>>>(x);
    // branch C (s1): attn -> csr
    k_attn<<<BATCH, 256, SMEM_ATTN, s1>>>(M, Ws);
    k_csr<<<BATCH, 512, 0, s1>>>(edst);

    // join convA into default stream before mm
    cudaEventRecord(e2, s2);
    cudaStreamWaitEvent(0, e2, 0);
    k_mm<<<dim3(MROWS/128, JW/128), 256>>>(bias, out);

    // join attn/csr before agg
    cudaEventRecord(e1, s1);
    cudaStreamWaitEvent(0, e1, 0);
    k_agg<<<(NTOT*32 + 127)/128, 128>>>(esrc, etyp, natt, out);
}

// round 8
// speedup vs baseline: 2.0263x; 1.2074x over previous
#include <cuda_runtime.h>
#include <cuda_fp16.h>
#include <cstdint>
#include <cstddef>

#define BATCH 64
#define T 90
#define O 5
#define D 256
#define H 256
#define EA 4096
#define R 5
#define NB 8
#define NPG 95
#define NTOT (BATCH*NPG)      /* 6080 */
#define JW 1536               /* 5*256 relation cols + 256 root cols */
#define XWC 1280              /* relation part of xW */
#define MROWS 6144            /* NTOT padded to 48*128 */
#define KP 256                /* single fp16 term */

// ---------------- device scratch ----------------
__device__ __align__(128) __half g_xWh[(size_t)NTOT*XWC];         // 15.6 MB fp16
__device__ __align__(128) float g_P[(size_t)BATCH*T*T];           // softmax probs
__device__ __align__(128) int   g_off[BATCH*(T+1)];
__device__ __align__(128) unsigned short g_eid[BATCH*EA];
__device__ __align__(128) __half g_Abf[(size_t)MROWS*KP];         // 3.1 MB  [row][k]
__device__ __align__(128) __half g_Bbf[(size_t)JW*KP];            // 0.8 MB  [n][k]

// ---------------- PTX helpers (baseline-PTX only: sm_80-class) ----------------
__device__ __forceinline__ uint32_t smem_u32(const void* p) {
    uint32_t a;
    asm("{ .reg .u64 t; cvta.to.shared.u64 t, %1; cvt.u32.u64 %0, t; }" : "=r"(a) : "l"(p));
    return a;
}
#define CP16(dst,src)    asm volatile("cp.async.cg.shared.global [%0], [%1], 16;"::"r"(dst),"l"(src):"memory")
#define CP_COMMIT()      asm volatile("cp.async.commit_group;":::"memory")
#define CP_WAIT(n)       asm volatile("cp.async.wait_group %0;"::"n"(n):"memory")
#define LDSM4(r0,r1,r2,r3,addr) \
    asm volatile("ldmatrix.sync.aligned.m8n8.x4.shared.b16 {%0,%1,%2,%3}, [%4];" \
                 : "=r"(r0),"=r"(r1),"=r"(r2),"=r"(r3) : "r"(addr))
#define MMA16816(c, a, b0, b1) \
    asm volatile("mma.sync.aligned.m16n8k16.row.col.f32.f16.f16.f32 " \
                 "{%0,%1,%2,%3},{%4,%5,%6,%7},{%8,%9},{%0,%1,%2,%3};" \
                 : "+f"((c)[0]),"+f"((c)[1]),"+f"((c)[2]),"+f"((c)[3]) \
                 : "r"((a)[0]),"r"((a)[1]),"r"((a)[2]),"r"((a)[3]),"r"(b0),"r"(b1))

// ---------------- K1: B' = W_hi,  W = [comp@bases | root] -----------------
__global__ void k_buildB(const float* __restrict__ bases,
                         const float* __restrict__ comp,
                         const float* __restrict__ root) {
    int idx = blockIdx.x*256 + threadIdx.x;     // 0 .. D*JW-1
    int d = idx / JW, j = idx - d*JW;
    float v;
    if (j < XWC) {
        int r = j >> 8, h = j & 255;
        float s = 0.f;
        #pragma unroll
        for (int n = 0; n < NB; n++)
            s += comp[r*NB + n] * bases[((size_t)n*D + d)*H + h];
        v = s;
    } else {
        v = root[d*H + (j - XWC)];
    }
    g_Bbf[(size_t)j*KP + d] = __float2half(v);
}

// ---------------- K1b: A' = x_hi ------------------------------------------
__global__ void k_convA(const float* __restrict__ x) {
    int idx = blockIdx.x*256 + threadIdx.x;   // 0 .. MROWS*256-1
    int row = idx >> 8, col = idx & 255;
    float v = (row < NTOT) ? x[(size_t)row*D + col] : 0.f;
    g_Abf[(size_t)row*KP + col] = __float2half(v);
}

// ---------------- K3: attention ------------------------------------------
__global__ void k_attn(const float* __restrict__ M, const float* __restrict__ Ws) {
    extern __shared__ float sm[];
    float* sM = sm;
    float* sW = sm + 96*257;
    float* sS = sm + 2*96*257;
    int b = blockIdx.x, tid = threadIdx.x;
    for (int q = tid; q < T*(D/4); q += 256) {
        int m = q >> 6, d4 = (q & 63) << 2;
        float4 v = *(const float4*)(M + ((size_t)b*T + m)*D + d4);
        float* p = sM + m*257 + d4;
        p[0]=v.x; p[1]=v.y; p[2]=v.z; p[3]=v.w;
    }
    for (int q = tid; q < T*(D/4); q += 256) {
        int m = q >> 6, d4 = (q & 63) << 2;
        float4 v = *(const float4*)(Ws + (size_t)m*D + d4);
        float* p = sW + m*257 + d4;
        p[0]=v.x; p[1]=v.y; p[2]=v.z; p[3]=v.w;
    }
    for (int q = tid; q < 6*257; q += 256) { sM[90*257 + q] = 0.f; sW[90*257 + q] = 0.f; }
    __syncthreads();
    int tx = tid & 15, ty = tid >> 4;
    int m0 = ty*6, s0 = tx*6;
    float acc[6][6];
    #pragma unroll
    for (int i = 0; i < 6; i++)
        #pragma unroll
        for (int j = 0; j < 6; j++) acc[i][j] = 0.f;
    for (int k = 0; k < D; k++) {
        float a[6], bb[6];
        #pragma unroll
        for (int i = 0; i < 6; i++) { a[i] = sM[(m0+i)*257 + k]; bb[i] = sW[(s0+i)*257 + k]; }
        #pragma unroll
        for (int i = 0; i < 6; i++)
            #pragma unroll
            for (int j = 0; j < 6; j++) acc[i][j] += a[i]*bb[j];
    }
    #pragma unroll
    for (int i = 0; i < 6; i++)
        #pragma unroll
        for (int j = 0; j < 6; j++) {
            int m = m0+i, s = s0+j;
            if (m < T && s < T) sS[m*91 + s] = acc[i][j];
        }
    __syncthreads();
    if (tid < T) {
        int s = tid;
        float mx = -1e30f;
        for (int t = 0; t < T; t++) mx = fmaxf(mx, sS[t*91 + s]);
        float den = 0.f;
        for (int t = 0; t < T; t++) den += __expf(sS[t*91 + s] - mx);
        float inv = 1.f/den;
        for (int t = 0; t < T; t++)
            g_P[((size_t)b*T + t)*T + s] = __expf(sS[t*91 + s] - mx) * inv;
    }
}

// ---------------- K4: CSR (512 threads for latency hiding) ----------------
__global__ void k_csr(const int* __restrict__ edge_dst) {
    __shared__ int cnt[T], offs[T+1], cur[T];
    int b = blockIdx.x, tid = threadIdx.x;   // 512 threads
    if (tid < T) cnt[tid] = 0;
    __syncthreads();
    #pragma unroll
    for (int q = 0; q < EA/512; q++) {
        int e = tid + q*512;
        atomicAdd(&cnt[edge_dst[(size_t)b*EA + e]], 1);
    }
    __syncthreads();
    if (tid == 0) {
        int a = 0;
        for (int i = 0; i < T; i++) { offs[i] = a; a += cnt[i]; }
        offs[T] = a;
    }
    __syncthreads();
    if (tid < T)  cur[tid] = offs[tid];
    if (tid <= T) g_off[b*(T+1) + tid] = offs[tid];
    __syncthreads();
    #pragma unroll
    for (int q = 0; q < EA/512; q++) {
        int e = tid + q*512;
        int dv = edge_dst[(size_t)b*EA + e];
        int pos = atomicAdd(&cur[dv], 1);
        g_eid[(size_t)b*EA + pos] = (unsigned short)e;
    }
}

// ---------------- K2: mma.sync fp16 GEMM ----------------------------------
// C[6144,1536] = A'[6144,256] @ B'[1536,256]^T
// 128x128 tile, BK=32, 8 warps (4x2), warp tile 32x64, double-buffered cp.async
#define SPITCH 40            /* smem row pitch in halves (80 B, conflict-free) */
#define STAGE_HALVES (128*SPITCH)
#define NKT (KP/32)          /* 8 */

__global__ void __launch_bounds__(256, 2) k_mm(const float* __restrict__ bias,
                                               float* __restrict__ out) {
    __shared__ __half sA[2][STAGE_HALVES];
    __shared__ __half sB[2][STAGE_HALVES];
    int tid = threadIdx.x, lane = tid & 31, wid = tid >> 5;
    int warpM = wid & 3, warpN = wid >> 2;
    int row0 = blockIdx.x * 128;
    int colTile = blockIdx.y, col0 = colTile * 128;

    uint32_t sbA = smem_u32(sA), sbB = smem_u32(sB);

    float c[2][8][4];
    #pragma unroll
    for (int mt = 0; mt < 2; mt++)
        #pragma unroll
        for (int nt = 0; nt < 8; nt++)
            #pragma unroll
            for (int q = 0; q < 4; q++) c[mt][nt][q] = 0.f;

    // per-thread load slots: 512 16B chunks per tile per matrix
    int lrow = tid >> 2, lseg = tid & 3;     // +256 -> rows 64..127
    const __half* gA = g_Abf + (size_t)(row0 + lrow)*KP + lseg*8;
    const __half* gB = g_Bbf + (size_t)(col0 + lrow)*KP + lseg*8;
    uint32_t dA = sbA + (lrow*SPITCH + lseg*8)*2;
    uint32_t dB = sbB + (lrow*SPITCH + lseg*8)*2;
    const int rstep = 64;  // +256 threads -> +64 rows

    // prologue: stage 0 (kt=0)
    {
        CP16(dA,                        (const char*)(gA));
        CP16(dA + rstep*SPITCH*2,       (const char*)(gA + (size_t)rstep*KP));
        CP16(dB,                        (const char*)(gB));
        CP16(dB + rstep*SPITCH*2,       (const char*)(gB + (size_t)rstep*KP));
        CP_COMMIT();
    }

    // ldmatrix address precompute (within-stage offsets)
    int aRow = warpM*32 + ((lane>>3)&1)*8 + (lane&7);     // + mt*16
    int aCol = ((lane>>4)&1)*8;                           // + ks*16
    int bRow = warpN*64 + ((lane>>4)&1)*8 + (lane&7);     // + ntp*16
    int bCol = ((lane>>3)&1)*8;                           // + ks*16
    uint32_t aAddr0 = sbA + (aRow*SPITCH + aCol)*2;
    uint32_t bAddr0 = sbB + (bRow*SPITCH + bCol)*2;

    for (int kt = 0; kt < NKT; kt++) {
        int s = kt & 1;
        if (kt + 1 < NKT) {
            int so = s ^ 1;
            size_t go = (size_t)(kt+1)*32;
            uint32_t soff = so * STAGE_HALVES * 2;
            CP16(dA + soff,                  (const char*)(gA + go));
            CP16(dA + soff + rstep*SPITCH*2, (const char*)(gA + go + (size_t)rstep*KP));
            CP16(dB + soff,                  (const char*)(gB + go));
            CP16(dB + soff + rstep*SPITCH*2, (const char*)(gB + go + (size_t)rstep*KP));
            CP_COMMIT();
            CP_WAIT(1);
        } else {
            CP_WAIT(0);
        }
        __syncthreads();

        uint32_t sa = aAddr0 + s * STAGE_HALVES * 2;
        uint32_t sb2 = bAddr0 + s * STAGE_HALVES * 2;
        #pragma unroll
        for (int ks = 0; ks < 2; ks++) {
            uint32_t a[2][4];
            LDSM4(a[0][0],a[0][1],a[0][2],a[0][3], sa + ks*32);           // m tile 0
            LDSM4(a[1][0],a[1][1],a[1][2],a[1][3], sa + ks*32 + 16*SPITCH*2); // m tile 1
            uint32_t b[8][2];
            #pragma unroll
            for (int ntp = 0; ntp < 4; ntp++) {
                uint32_t r0,r1,r2,r3;
                LDSM4(r0,r1,r2,r3, sb2 + ks*32 + ntp*16*SPITCH*2);
                b[ntp*2+0][0]=r0; b[ntp*2+0][1]=r1;
                b[ntp*2+1][0]=r2; b[ntp*2+1][1]=r3;
            }
            #pragma unroll
            for (int mt = 0; mt < 2; mt++)
                #pragma unroll
                for (int nt = 0; nt < 8; nt++)
                    MMA16816(c[mt][nt], a[mt], b[nt][0], b[nt][1]);
        }
        __syncthreads();
    }

    // epilogue: relation cols -> g_xWh (fp16) ; root cols -> out (fp32 + bias)
    int gr = lane >> 2, ci = lane & 3;
    #pragma unroll
    for (int mt = 0; mt < 2; mt++) {
        int r0w = row0 + warpM*32 + mt*16 + gr;
        #pragma unroll
        for (int nt = 0; nt < 8; nt++) {
            int col = col0 + warpN*64 + nt*8 + ci*2;
            if (colTile < 10) {
                if (r0w < NTOT)
                    *(__half2*)(g_xWh + (size_t)r0w*XWC + col) =
                        __floats2half2_rn(c[mt][nt][0], c[mt][nt][1]);
                if (r0w + 8 < NTOT)
                    *(__half2*)(g_xWh + (size_t)(r0w+8)*XWC + col) =
                        __floats2half2_rn(c[mt][nt][2], c[mt][nt][3]);
            } else {
                int h = col - XWC;
                float b0 = bias[h], b1 = bias[h+1];
                if (r0w < NTOT)
                    *(float2*)(out + (size_t)r0w*H + h) = make_float2(c[mt][nt][0] + b0, c[mt][nt][1] + b1);
                if (r0w + 8 < NTOT)
                    *(float2*)(out + (size_t)(r0w+8)*H + h) = make_float2(c[mt][nt][2] + b0, c[mt][nt][3] + b1);
            }
        }
    }
}

// ---------------- K5: warp-per-node aggregation (fp16 gather) -------------
__device__ __forceinline__ void fma8(float* acc, const uint4& v, float norm) {
    const __half2* hv = (const __half2*)&v;
    #pragma unroll
    for (int q = 0; q < 4; q++) {
        float2 f = __half22float2(hv[q]);
        acc[q*2+0] += norm * f.x;
        acc[q*2+1] += norm * f.y;
    }
}

__global__ void k_agg(const int* __restrict__ edge_src,
                      const int* __restrict__ edge_type,
                      const float* __restrict__ node_att,
                      float* __restrict__ out) {
    int w = (blockIdx.x*blockDim.x + threadIdx.x) >> 5;
    int l = threadIdx.x & 31;
    if (w >= NTOT) return;
    int b = w / NPG, dn = w - b*NPG;

    float acc[8];
    {   // base = x@root + bias (written by k_mm)
        float4 v0 = *(const float4*)(out + (size_t)w*H + l*8);
        float4 v1 = *(const float4*)(out + (size_t)w*H + l*8 + 4);
        acc[0]=v0.x; acc[1]=v0.y; acc[2]=v0.z; acc[3]=v0.w;
        acc[4]=v1.x; acc[5]=v1.y; acc[6]=v1.z; acc[7]=v1.w;
    }

    if (dn < T) {
        int i0 = g_off[b*(T+1) + dn];
        int i1 = g_off[b*(T+1) + dn + 1];
        const float* Pd = g_P + ((size_t)b*T + dn)*T;
        const int* esrc = edge_src + (size_t)b*EA;
        const int* etyp = edge_type + (size_t)b*EA;
        const unsigned short* eid = g_eid + (size_t)b*EA;
        for (int i = i0; i < i1; i++) {
            int e   = eid[i];
            int src = esrc[e];
            int ty  = etyp[e];
            float norm = Pd[src];
            const __half* p = g_xWh + ((size_t)(b*NPG + src)*XWC + ty*H);
            uint4 v = *(const uint4*)(p + l*8);
            fma8(acc, v, norm);
        }
    } else {
        int o = dn - T;   // user node: edges i -> T+o, type R-1, norm = node_att[b,i,o]
        const float* na = node_att + (size_t)b*T*O + o;
        #pragma unroll 2
        for (int i = 0; i < T; i++) {
            float norm = na[i*O];
            const __half* p = g_xWh + ((size_t)(b*NPG + i)*XWC + (R-1)*H);
            uint4 v = *(const uint4*)(p + l*8);
            fma8(acc, v, norm);
        }
    }
    *(float4*)(out + (size_t)w*H + l*8)     = make_float4(acc[0], acc[1], acc[2], acc[3]);
    *(float4*)(out + (size_t)w*H + l*8 + 4) = make_float4(acc[4], acc[5], acc[6], acc[7]);
}

// ---------------- launch (fork-join graph concurrency) --------------------
extern "C" void kernel_launch(void* const* d_in, const int* in_sizes, int n_in,
                              void* d_out, int out_size) {
    const float* M     = (const float*)d_in[0];
    const float* x     = (const float*)d_in[1];
    const float* natt  = (const float*)d_in[2];
    const float* Ws    = (const float*)d_in[3];
    const float* bases = (const float*)d_in[4];
    const float* comp  = (const float*)d_in[5];
    const float* root  = (const float*)d_in[6];
    const float* bias  = (const float*)d_in[7];
    const int* esrc    = (const int*)d_in[8];
    const int* edst    = (const int*)d_in[9];
    const int* etyp    = (const int*)d_in[10];
    float* out = (float*)d_out;

    static cudaStream_t s1 = nullptr, s2 = nullptr;
    static cudaEvent_t  ef = nullptr, e1 = nullptr, e2 = nullptr;
    static bool attr_done = false;
    if (!s1) {
        cudaStreamCreateWithFlags(&s1, cudaStreamNonBlocking);
        cudaStreamCreateWithFlags(&s2, cudaStreamNonBlocking);
        cudaEventCreateWithFlags(&ef, cudaEventDisableTiming);
        cudaEventCreateWithFlags(&e1, cudaEventDisableTiming);
        cudaEventCreateWithFlags(&e2, cudaEventDisableTiming);
    }
    if (!attr_done) {
        const int SMEM_ATTN = (2*96*257 + 90*91)*(int)sizeof(float);
        cudaFuncSetAttribute(k_attn, cudaFuncAttributeMaxDynamicSharedMemorySize, SMEM_ATTN);
        attr_done = true;
    }
    const int SMEM_ATTN = (2*96*257 + 90*91)*(int)sizeof(float);

    // fork from capture-origin (default) stream
    cudaEventRecord(ef, 0);
    cudaStreamWaitEvent(s1, ef, 0);
    cudaStreamWaitEvent(s2, ef, 0);

    // branch A (default stream): buildB -> (join convA) -> mm
    k_buildB<<<(D*JW)/256, 256>>>(bases, comp, root);
    // branch B (s2): convA
    k_convA<<<(MROWS*256)/256, 256, 0, s2>>>(x);
    // branch C (s1): attn -> csr
    k_attn<<<BATCH, 256, SMEM_ATTN, s1>>>(M, Ws);
    k_csr<<<BATCH, 512, 0, s1>>>(edst);

    // join convA into default stream before mm
    cudaEventRecord(e2, s2);
    cudaStreamWaitEvent(0, e2, 0);
    k_mm<<<dim3(MROWS/128, JW/128), 256>>>(bias, out);

    // join attn/csr before agg
    cudaEventRecord(e1, s1);
    cudaStreamWaitEvent(0, e1, 0);
    k_agg<<<(NTOT*32 + 127)/128, 128>>>(esrc, etyp, natt, out);
}

// round 9
// speedup vs baseline: 2.4733x; 1.2206x over previous
#include <cuda_runtime.h>
#include <cuda_fp16.h>
#include <cstdint>
#include <cstddef>

#define BATCH 64
#define T 90
#define O 5
#define D 256
#define H 256
#define EA 4096
#define R 5
#define NB 8
#define NPG 95
#define NTOT (BATCH*NPG)      /* 6080 */
#define JW 1536               /* 5*256 relation cols + 256 root cols */
#define XWC 1280              /* relation part of xW */
#define MROWS 6144            /* NTOT padded to 48*128 */
#define KP 256                /* single fp16 term */

// ---------------- device scratch ----------------
__device__ __align__(128) __half g_xWh[(size_t)NTOT*XWC];         // 15.6 MB fp16
__device__ __align__(128) float g_P[(size_t)BATCH*T*T];           // softmax probs
__device__ __align__(128) __half g_Abf[(size_t)MROWS*KP];         // 3.1 MB  [row][k]
__device__ __align__(128) __half g_Bbf[(size_t)JW*KP];            // 0.8 MB  [n][k]

// ---------------- PTX helpers (baseline-PTX only: sm_80-class) ----------------
__device__ __forceinline__ uint32_t smem_u32(const void* p) {
    uint32_t a;
    asm("{ .reg .u64 t; cvta.to.shared.u64 t, %1; cvt.u32.u64 %0, t; }" : "=r"(a) : "l"(p));
    return a;
}
#define CP16(dst,src)    asm volatile("cp.async.cg.shared.global [%0], [%1], 16;"::"r"(dst),"l"(src):"memory")
#define CP_COMMIT()      asm volatile("cp.async.commit_group;":::"memory")
#define CP_WAIT(n)       asm volatile("cp.async.wait_group %0;"::"n"(n):"memory")
#define LDSM4(r0,r1,r2,r3,addr) \
    asm volatile("ldmatrix.sync.aligned.m8n8.x4.shared.b16 {%0,%1,%2,%3}, [%4];" \
                 : "=r"(r0),"=r"(r1),"=r"(r2),"=r"(r3) : "r"(addr))
#define LDSM4T(r0,r1,r2,r3,addr) \
    asm volatile("ldmatrix.sync.aligned.m8n8.x4.trans.shared.b16 {%0,%1,%2,%3}, [%4];" \
                 : "=r"(r0),"=r"(r1),"=r"(r2),"=r"(r3) : "r"(addr))
#define MMA16816(c, a, b0, b1) \
    asm volatile("mma.sync.aligned.m16n8k16.row.col.f32.f16.f16.f32 " \
                 "{%0,%1,%2,%3},{%4,%5,%6,%7},{%8,%9},{%0,%1,%2,%3};" \
                 : "+f"((c)[0]),"+f"((c)[1]),"+f"((c)[2]),"+f"((c)[3]) \
                 : "r"((a)[0]),"r"((a)[1]),"r"((a)[2]),"r"((a)[3]),"r"(b0),"r"(b1))

// ---------------- K1: B' = W_hi,  W = [comp@bases | root] -----------------
__global__ void k_buildB(const float* __restrict__ bases,
                         const float* __restrict__ comp,
                         const float* __restrict__ root) {
    int idx = blockIdx.x*256 + threadIdx.x;     // 0 .. D*JW-1
    int d = idx / JW, j = idx - d*JW;
    float v;
    if (j < XWC) {
        int r = j >> 8, h = j & 255;
        float s = 0.f;
        #pragma unroll
        for (int n = 0; n < NB; n++)
            s += comp[r*NB + n] * bases[((size_t)n*D + d)*H + h];
        v = s;
    } else {
        v = root[d*H + (j - XWC)];
    }
    g_Bbf[(size_t)j*KP + d] = __float2half(v);
}

// ---------------- K1b: A' = x_hi ------------------------------------------
__global__ void k_convA(const float* __restrict__ x) {
    int idx = blockIdx.x*256 + threadIdx.x;   // 0 .. MROWS*256-1
    int row = idx >> 8, col = idx & 255;
    float v = (row < NTOT) ? x[(size_t)row*D + col] : 0.f;
    g_Abf[(size_t)row*KP + col] = __float2half(v);
}

// ---------------- K3: attention ------------------------------------------
__global__ void k_attn(const float* __restrict__ M, const float* __restrict__ Ws) {
    extern __shared__ float sm[];
    float* sM = sm;
    float* sW = sm + 96*257;
    float* sS = sm + 2*96*257;
    int b = blockIdx.x, tid = threadIdx.x;
    for (int q = tid; q < T*(D/4); q += 256) {
        int m = q >> 6, d4 = (q & 63) << 2;
        float4 v = *(const float4*)(M + ((size_t)b*T + m)*D + d4);
        float* p = sM + m*257 + d4;
        p[0]=v.x; p[1]=v.y; p[2]=v.z; p[3]=v.w;
    }
    for (int q = tid; q < T*(D/4); q += 256) {
        int m = q >> 6, d4 = (q & 63) << 2;
        float4 v = *(const float4*)(Ws + (size_t)m*D + d4);
        float* p = sW + m*257 + d4;
        p[0]=v.x; p[1]=v.y; p[2]=v.z; p[3]=v.w;
    }
    for (int q = tid; q < 6*257; q += 256) { sM[90*257 + q] = 0.f; sW[90*257 + q] = 0.f; }
    __syncthreads();
    int tx = tid & 15, ty = tid >> 4;
    int m0 = ty*6, s0 = tx*6;
    float acc[6][6];
    #pragma unroll
    for (int i = 0; i < 6; i++)
        #pragma unroll
        for (int j = 0; j < 6; j++) acc[i][j] = 0.f;
    for (int k = 0; k < D; k++) {
        float a[6], bb[6];
        #pragma unroll
        for (int i = 0; i < 6; i++) { a[i] = sM[(m0+i)*257 + k]; bb[i] = sW[(s0+i)*257 + k]; }
        #pragma unroll
        for (int i = 0; i < 6; i++)
            #pragma unroll
            for (int j = 0; j < 6; j++) acc[i][j] += a[i]*bb[j];
    }
    #pragma unroll
    for (int i = 0; i < 6; i++)
        #pragma unroll
        for (int j = 0; j < 6; j++) {
            int m = m0+i, s = s0+j;
            if (m < T && s < T) sS[m*91 + s] = acc[i][j];
        }
    __syncthreads();
    if (tid < T) {
        int s = tid;
        float mx = -1e30f;
        for (int t = 0; t < T; t++) mx = fmaxf(mx, sS[t*91 + s]);
        float den = 0.f;
        for (int t = 0; t < T; t++) den += __expf(sS[t*91 + s] - mx);
        float inv = 1.f/den;
        for (int t = 0; t < T; t++)
            g_P[((size_t)b*T + t)*T + s] = __expf(sS[t*91 + s] - mx) * inv;
    }
}

// ---------------- K2: mma.sync fp16 GEMM ----------------------------------
// C[6144,1536] = A'[6144,256] @ B'[1536,256]^T
#define SPITCH 40            /* smem row pitch in halves (80 B, conflict-free) */
#define STAGE_HALVES (128*SPITCH)
#define NKT (KP/32)          /* 8 */

__global__ void __launch_bounds__(256, 2) k_mm(const float* __restrict__ bias,
                                               float* __restrict__ out) {
    __shared__ __half sA[2][STAGE_HALVES];
    __shared__ __half sB[2][STAGE_HALVES];
    int tid = threadIdx.x, lane = tid & 31, wid = tid >> 5;
    int warpM = wid & 3, warpN = wid >> 2;
    int row0 = blockIdx.x * 128;
    int colTile = blockIdx.y, col0 = colTile * 128;

    uint32_t sbA = smem_u32(sA), sbB = smem_u32(sB);

    float c[2][8][4];
    #pragma unroll
    for (int mt = 0; mt < 2; mt++)
        #pragma unroll
        for (int nt = 0; nt < 8; nt++)
            #pragma unroll
            for (int q = 0; q < 4; q++) c[mt][nt][q] = 0.f;

    int lrow = tid >> 2, lseg = tid & 3;
    const __half* gA = g_Abf + (size_t)(row0 + lrow)*KP + lseg*8;
    const __half* gB = g_Bbf + (size_t)(col0 + lrow)*KP + lseg*8;
    uint32_t dA = sbA + (lrow*SPITCH + lseg*8)*2;
    uint32_t dB = sbB + (lrow*SPITCH + lseg*8)*2;
    const int rstep = 64;

    {
        CP16(dA,                        (const char*)(gA));
        CP16(dA + rstep*SPITCH*2,       (const char*)(gA + (size_t)rstep*KP));
        CP16(dB,                        (const char*)(gB));
        CP16(dB + rstep*SPITCH*2,       (const char*)(gB + (size_t)rstep*KP));
        CP_COMMIT();
    }

    int aRow = warpM*32 + ((lane>>3)&1)*8 + (lane&7);
    int aCol = ((lane>>4)&1)*8;
    int bRow = warpN*64 + ((lane>>4)&1)*8 + (lane&7);
    int bCol = ((lane>>3)&1)*8;
    uint32_t aAddr0 = sbA + (aRow*SPITCH + aCol)*2;
    uint32_t bAddr0 = sbB + (bRow*SPITCH + bCol)*2;

    for (int kt = 0; kt < NKT; kt++) {
        int s = kt & 1;
        if (kt + 1 < NKT) {
            int so = s ^ 1;
            size_t go = (size_t)(kt+1)*32;
            uint32_t soff = so * STAGE_HALVES * 2;
            CP16(dA + soff,                  (const char*)(gA + go));
            CP16(dA + soff + rstep*SPITCH*2, (const char*)(gA + go + (size_t)rstep*KP));
            CP16(dB + soff,                  (const char*)(gB + go));
            CP16(dB + soff + rstep*SPITCH*2, (const char*)(gB + go + (size_t)rstep*KP));
            CP_COMMIT();
            CP_WAIT(1);
        } else {
            CP_WAIT(0);
        }
        __syncthreads();

        uint32_t sa = aAddr0 + s * STAGE_HALVES * 2;
        uint32_t sb2 = bAddr0 + s * STAGE_HALVES * 2;
        #pragma unroll
        for (int ks = 0; ks < 2; ks++) {
            uint32_t a[2][4];
            LDSM4(a[0][0],a[0][1],a[0][2],a[0][3], sa + ks*32);
            LDSM4(a[1][0],a[1][1],a[1][2],a[1][3], sa + ks*32 + 16*SPITCH*2);
            uint32_t b[8][2];
            #pragma unroll
            for (int ntp = 0; ntp < 4; ntp++) {
                uint32_t r0,r1,r2,r3;
                LDSM4(r0,r1,r2,r3, sb2 + ks*32 + ntp*16*SPITCH*2);
                b[ntp*2+0][0]=r0; b[ntp*2+0][1]=r1;
                b[ntp*2+1][0]=r2; b[ntp*2+1][1]=r3;
            }
            #pragma unroll
            for (int mt = 0; mt < 2; mt++)
                #pragma unroll
                for (int nt = 0; nt < 8; nt++)
                    MMA16816(c[mt][nt], a[mt], b[nt][0], b[nt][1]);
        }
        __syncthreads();
    }

    int gr = lane >> 2, ci = lane & 3;
    #pragma unroll
    for (int mt = 0; mt < 2; mt++) {
        int r0w = row0 + warpM*32 + mt*16 + gr;
        #pragma unroll
        for (int nt = 0; nt < 8; nt++) {
            int col = col0 + warpN*64 + nt*8 + ci*2;
            if (colTile < 10) {
                if (r0w < NTOT)
                    *(__half2*)(g_xWh + (size_t)r0w*XWC + col) =
                        __floats2half2_rn(c[mt][nt][0], c[mt][nt][1]);
                if (r0w + 8 < NTOT)
                    *(__half2*)(g_xWh + (size_t)(r0w+8)*XWC + col) =
                        __floats2half2_rn(c[mt][nt][2], c[mt][nt][3]);
            } else {
                int h = col - XWC;
                float b0 = bias[h], b1 = bias[h+1];
                if (r0w < NTOT)
                    *(float2*)(out + (size_t)r0w*H + h) = make_float2(c[mt][nt][0] + b0, c[mt][nt][1] + b1);
                if (r0w + 8 < NTOT)
                    *(float2*)(out + (size_t)(r0w+8)*H + h) = make_float2(c[mt][nt][2] + b0, c[mt][nt][3] + b1);
            }
        }
    }
}

// ---------------- K5: dense per-graph edge GEMM ---------------------------
// agg[b] (96x256) = C[b] (96x464) @ xWflat[b] (464x256), 2 CTAs/graph (n halves)
#define CPITCH 472           /* C row pitch in halves */
#define BPITCH 136           /* B tile row pitch in halves (128 data + 8 pad) */
#define KTILES 29            /* ceil(450/16) */
#define BSTAGE (16*BPITCH*2) /* 4352 B per stage */
#define AGG_SMEM (96*CPITCH*2 + 2*BSTAGE)   /* 90624 + 8704 = 99328 */

__global__ void __launch_bounds__(256, 1) k_agg2(const int* __restrict__ edge_src,
                                                 const int* __restrict__ edge_dst,
                                                 const int* __restrict__ edge_type,
                                                 const float* __restrict__ node_att,
                                                 float* __restrict__ out) {
    extern __shared__ __half sm2[];
    __half* Cm = sm2;                          // [96][CPITCH]
    uint32_t sbC = smem_u32(Cm);
    uint32_t sbB = sbC + 96*CPITCH*2;          // 2 stages [16][BPITCH]
    int b = blockIdx.x >> 1, nh = blockIdx.x & 1;
    int tid = threadIdx.x, lane = tid & 31, w = tid >> 5;
    int n0 = nh * 128;

    // zero C (incl. padding cols)
    uint4 z = make_uint4(0,0,0,0);
    for (int i = tid; i < 96*CPITCH/8; i += 256) ((uint4*)Cm)[i] = z;
    __syncthreads();

    // scatter attention edges: C[dst][src*R+ty] += P[b][dst][src]
    #pragma unroll
    for (int q = 0; q < EA/256; q++) {
        int e = tid + q*256;
        int src = edge_src[(size_t)b*EA + e];
        int dst = edge_dst[(size_t)b*EA + e];
        int ty  = edge_type[(size_t)b*EA + e];
        float norm = g_P[((size_t)b*T + dst)*T + src];
        atomicAdd(&Cm[dst*CPITCH + src*R + ty], __float2half(norm));
    }
    // tag entries: C[T+o][src*R+(R-1)] = node_att[b][src][o]  (rows 90..94, unique)
    for (int q = tid; q < T*O; q += 256) {
        int src = q / O, o = q - src*O;
        Cm[(T+o)*CPITCH + src*R + (R-1)] = __float2half(node_att[((size_t)b*T + src)*O + o]);
    }

    // B tile loader: stage s, ktile kt. 256 threads: row=t>>4 (16 rows), ch=t&15 (16B chunks)
    int lrow = tid >> 4, lch = tid & 15;
    uint32_t dBs = sbB + lrow*(BPITCH*2) + lch*16;
    // prologue kt=0
    {
        int k = lrow;
        int src = k / R, ty = k - src*R;
        const __half* sp = g_xWh + ((size_t)(b*NPG + src)*XWC + ty*H + n0) + lch*8;
        CP16(dBs, (const char*)sp);
        CP_COMMIT();
    }

    float acc[6][2][4];
    #pragma unroll
    for (int mt = 0; mt < 6; mt++)
        #pragma unroll
        for (int nt = 0; nt < 2; nt++)
            #pragma unroll
            for (int q = 0; q < 4; q++) acc[mt][nt][q] = 0.f;

    // ldmatrix addresses
    uint32_t aAddr = sbC + ((((lane>>3)&1)*8 + (lane&7))*CPITCH + ((lane>>4)&1)*8)*2;  // + mt*16*CPITCH*2 + kt*32
    uint32_t bAddr = (((lane>>3)&1)*8 + (lane&7))*(BPITCH*2) + (w*16 + ((lane>>4)&1)*8)*2; // + stage base

    for (int kt = 0; kt < KTILES; kt++) {
        int s = kt & 1;
        if (kt + 1 < KTILES) {
            int k = (kt+1)*16 + lrow;
            int src = k / R, ty = k - src*R;
            const __half* sp = g_xWh + ((size_t)(b*NPG + src)*XWC + ty*H + n0) + lch*8;
            CP16(dBs + (s^1)*BSTAGE, (const char*)sp);
            CP_COMMIT();
            CP_WAIT(1);
        } else {
            CP_WAIT(0);
        }
        __syncthreads();

        uint32_t bb0, bb1, bb2, bb3;
        LDSM4T(bb0, bb1, bb2, bb3, sbB + s*BSTAGE + bAddr);
        #pragma unroll
        for (int mt = 0; mt < 6; mt++) {
            uint32_t a[4];
            LDSM4(a[0], a[1], a[2], a[3], aAddr + mt*16*CPITCH*2 + kt*32);
            MMA16816(acc[mt][0], a, bb0, bb1);
            MMA16816(acc[mt][1], a, bb2, bb3);
        }
        __syncthreads();
    }

    // epilogue: out[node] += acc  (each CTA owns its n-half exclusively)
    int gr = lane >> 2, ci = lane & 3;
    #pragma unroll
    for (int mt = 0; mt < 6; mt++) {
        #pragma unroll
        for (int hrow = 0; hrow < 2; hrow++) {
            int row = mt*16 + gr + hrow*8;
            if (row < NPG) {
                size_t node = (size_t)b*NPG + row;
                #pragma unroll
                for (int nt = 0; nt < 2; nt++) {
                    int col = n0 + w*16 + nt*8 + ci*2;
                    float2* p = (float2*)(out + node*H + col);
                    float2 v = *p;
                    v.x += acc[mt][nt][hrow*2 + 0];
                    v.y += acc[mt][nt][hrow*2 + 1];
                    *p = v;
                }
            }
        }
    }
}

// ---------------- launch (fork-join graph concurrency) --------------------
extern "C" void kernel_launch(void* const* d_in, const int* in_sizes, int n_in,
                              void* d_out, int out_size) {
    const float* M     = (const float*)d_in[0];
    const float* x     = (const float*)d_in[1];
    const float* natt  = (const float*)d_in[2];
    const float* Ws    = (const float*)d_in[3];
    const float* bases = (const float*)d_in[4];
    const float* comp  = (const float*)d_in[5];
    const float* root  = (const float*)d_in[6];
    const float* bias  = (const float*)d_in[7];
    const int* esrc    = (const int*)d_in[8];
    const int* edst    = (const int*)d_in[9];
    const int* etyp    = (const int*)d_in[10];
    float* out = (float*)d_out;

    static cudaStream_t s1 = nullptr, s2 = nullptr;
    static cudaEvent_t  ef = nullptr, e1 = nullptr, e2 = nullptr;
    static bool attr_done = false;
    if (!s1) {
        cudaStreamCreateWithFlags(&s1, cudaStreamNonBlocking);
        cudaStreamCreateWithFlags(&s2, cudaStreamNonBlocking);
        cudaEventCreateWithFlags(&ef, cudaEventDisableTiming);
        cudaEventCreateWithFlags(&e1, cudaEventDisableTiming);
        cudaEventCreateWithFlags(&e2, cudaEventDisableTiming);
    }
    if (!attr_done) {
        const int SMEM_ATTN = (2*96*257 + 90*91)*(int)sizeof(float);
        cudaFuncSetAttribute(k_attn, cudaFuncAttributeMaxDynamicSharedMemorySize, SMEM_ATTN);
        cudaFuncSetAttribute(k_agg2, cudaFuncAttributeMaxDynamicSharedMemorySize, AGG_SMEM);
        attr_done = true;
    }
    const int SMEM_ATTN = (2*96*257 + 90*91)*(int)sizeof(float);

    // fork from capture-origin (default) stream
    cudaEventRecord(ef, 0);
    cudaStreamWaitEvent(s1, ef, 0);
    cudaStreamWaitEvent(s2, ef, 0);

    // branch A (default stream): buildB -> (join convA) -> mm
    k_buildB<<<(D*JW)/256, 256>>>(bases, comp, root);
    // branch B (s2): convA
    k_convA<<<(MROWS*256)/256, 256, 0, s2>>>(x);
    // branch C (s1): attn
    k_attn<<<BATCH, 256, SMEM_ATTN, s1>>>(M, Ws);

    // join convA into default stream before mm
    cudaEventRecord(e2, s2);
    cudaStreamWaitEvent(0, e2, 0);
    k_mm<<<dim3(MROWS/128, JW/128), 256>>>(bias, out);

    // join attn before agg2
    cudaEventRecord(e1, s1);
    cudaStreamWaitEvent(0, e1, 0);
    k_agg2<<<2*BATCH, 256, AGG_SMEM>>>(esrc, edst, etyp, natt, out);
}

// round 10
// speedup vs baseline: 2.5383x; 1.0263x over previous
#include <cuda_runtime.h>
#include <cuda_fp16.h>
#include <cstdint>
#include <cstddef>

#define BATCH 64
#define T 90
#define O 5
#define D 256
#define H 256
#define EA 4096
#define R 5
#define NB 8
#define NPG 95
#define NTOT (BATCH*NPG)      /* 6080 */
#define JW 1536               /* 5*256 relation cols + 256 root cols */
#define XWC 1280              /* relation part of xW */
#define MROWS 6144            /* NTOT padded to 48*128 */
#define KP 256                /* single fp16 term */

// ---------------- device scratch ----------------
__device__ __align__(128) __half g_xWh[(size_t)NTOT*XWC];         // 15.6 MB fp16
__device__ __align__(128) float g_P[(size_t)BATCH*T*T];           // softmax probs
__device__ __align__(128) __half g_Abf[(size_t)MROWS*KP];         // 3.1 MB  [row][k]
__device__ __align__(128) __half g_Bbf[(size_t)JW*KP];            // 0.8 MB  [n][k]

// ---------------- PTX helpers (baseline-PTX only: sm_80-class) ----------------
__device__ __forceinline__ uint32_t smem_u32(const void* p) {
    uint32_t a;
    asm("{ .reg .u64 t; cvta.to.shared.u64 t, %1; cvt.u32.u64 %0, t; }" : "=r"(a) : "l"(p));
    return a;
}
#define CP16(dst,src)    asm volatile("cp.async.cg.shared.global [%0], [%1], 16;"::"r"(dst),"l"(src):"memory")
#define CP_COMMIT()      asm volatile("cp.async.commit_group;":::"memory")
#define CP_WAIT(n)       asm volatile("cp.async.wait_group %0;"::"n"(n):"memory")
#define LDSM4(r0,r1,r2,r3,addr) \
    asm volatile("ldmatrix.sync.aligned.m8n8.x4.shared.b16 {%0,%1,%2,%3}, [%4];" \
                 : "=r"(r0),"=r"(r1),"=r"(r2),"=r"(r3) : "r"(addr))
#define LDSM4T(r0,r1,r2,r3,addr) \
    asm volatile("ldmatrix.sync.aligned.m8n8.x4.trans.shared.b16 {%0,%1,%2,%3}, [%4];" \
                 : "=r"(r0),"=r"(r1),"=r"(r2),"=r"(r3) : "r"(addr))
#define MMA16816(c, a, b0, b1) \
    asm volatile("mma.sync.aligned.m16n8k16.row.col.f32.f16.f16.f32 " \
                 "{%0,%1,%2,%3},{%4,%5,%6,%7},{%8,%9},{%0,%1,%2,%3};" \
                 : "+f"((c)[0]),"+f"((c)[1]),"+f"((c)[2]),"+f"((c)[3]) \
                 : "r"((a)[0]),"r"((a)[1]),"r"((a)[2]),"r"((a)[3]),"r"(b0),"r"(b1))

// ---------------- K1: B' = W_hi,  W = [comp@bases | root] -----------------
__global__ void k_buildB(const float* __restrict__ bases,
                         const float* __restrict__ comp,
                         const float* __restrict__ root) {
    int idx = blockIdx.x*256 + threadIdx.x;     // 0 .. D*JW-1
    int d = idx / JW, j = idx - d*JW;
    float v;
    if (j < XWC) {
        int r = j >> 8, h = j & 255;
        float s = 0.f;
        #pragma unroll
        for (int n = 0; n < NB; n++)
            s += comp[r*NB + n] * bases[((size_t)n*D + d)*H + h];
        v = s;
    } else {
        v = root[d*H + (j - XWC)];
    }
    g_Bbf[(size_t)j*KP + d] = __float2half(v);
}

// ---------------- K1b: A' = x_hi ------------------------------------------
__global__ void k_convA(const float* __restrict__ x) {
    int idx = blockIdx.x*256 + threadIdx.x;   // 0 .. MROWS*256-1
    int row = idx >> 8, col = idx & 255;
    float v = (row < NTOT) ? x[(size_t)row*D + col] : 0.f;
    g_Abf[(size_t)row*KP + col] = __float2half(v);
}

// ---------------- K3: attention ------------------------------------------
__global__ void k_attn(const float* __restrict__ M, const float* __restrict__ Ws) {
    extern __shared__ float sm[];
    float* sM = sm;
    float* sW = sm + 96*257;
    float* sS = sm + 2*96*257;
    int b = blockIdx.x, tid = threadIdx.x;
    for (int q = tid; q < T*(D/4); q += 256) {
        int m = q >> 6, d4 = (q & 63) << 2;
        float4 v = *(const float4*)(M + ((size_t)b*T + m)*D + d4);
        float* p = sM + m*257 + d4;
        p[0]=v.x; p[1]=v.y; p[2]=v.z; p[3]=v.w;
    }
    for (int q = tid; q < T*(D/4); q += 256) {
        int m = q >> 6, d4 = (q & 63) << 2;
        float4 v = *(const float4*)(Ws + (size_t)m*D + d4);
        float* p = sW + m*257 + d4;
        p[0]=v.x; p[1]=v.y; p[2]=v.z; p[3]=v.w;
    }
    for (int q = tid; q < 6*257; q += 256) { sM[90*257 + q] = 0.f; sW[90*257 + q] = 0.f; }
    __syncthreads();
    int tx = tid & 15, ty = tid >> 4;
    int m0 = ty*6, s0 = tx*6;
    float acc[6][6];
    #pragma unroll
    for (int i = 0; i < 6; i++)
        #pragma unroll
        for (int j = 0; j < 6; j++) acc[i][j] = 0.f;
    for (int k = 0; k < D; k++) {
        float a[6], bb[6];
        #pragma unroll
        for (int i = 0; i < 6; i++) { a[i] = sM[(m0+i)*257 + k]; bb[i] = sW[(s0+i)*257 + k]; }
        #pragma unroll
        for (int i = 0; i < 6; i++)
            #pragma unroll
            for (int j = 0; j < 6; j++) acc[i][j] += a[i]*bb[j];
    }
    #pragma unroll
    for (int i = 0; i < 6; i++)
        #pragma unroll
        for (int j = 0; j < 6; j++) {
            int m = m0+i, s = s0+j;
            if (m < T && s < T) sS[m*91 + s] = acc[i][j];
        }
    __syncthreads();
    if (tid < T) {
        int s = tid;
        float mx = -1e30f;
        for (int t = 0; t < T; t++) mx = fmaxf(mx, sS[t*91 + s]);
        float den = 0.f;
        for (int t = 0; t < T; t++) den += __expf(sS[t*91 + s] - mx);
        float inv = 1.f/den;
        for (int t = 0; t < T; t++)
            g_P[((size_t)b*T + t)*T + s] = __expf(sS[t*91 + s] - mx) * inv;
    }
}

// ---------------- K2: mma.sync fp16 GEMM, 4-stage pipeline ----------------
// C[6144,1536] = A'[6144,256] @ B'[1536,256]^T
#define SPITCH 40            /* smem row pitch in halves (80 B, conflict-free) */
#define STAGE_HALVES (128*SPITCH)
#define NKT (KP/32)          /* 8 */
#define NSTAGE 4
#define MM_SMEM (2*NSTAGE*STAGE_HALVES*2)   /* A + B, 4 stages: 81920 B */

__global__ void __launch_bounds__(256, 2) k_mm(const float* __restrict__ bias,
                                               float* __restrict__ out) {
    extern __shared__ __half smm[];
    uint32_t sbA = smem_u32(smm);
    uint32_t sbB = sbA + NSTAGE*STAGE_HALVES*2;
    int tid = threadIdx.x, lane = tid & 31, wid = tid >> 5;
    int warpM = wid & 3, warpN = wid >> 2;
    int row0 = blockIdx.x * 128;
    int colTile = blockIdx.y, col0 = colTile * 128;

    float c[2][8][4];
    #pragma unroll
    for (int mt = 0; mt < 2; mt++)
        #pragma unroll
        for (int nt = 0; nt < 8; nt++)
            #pragma unroll
            for (int q = 0; q < 4; q++) c[mt][nt][q] = 0.f;

    int lrow = tid >> 2, lseg = tid & 3;
    const __half* gA = g_Abf + (size_t)(row0 + lrow)*KP + lseg*8;
    const __half* gB = g_Bbf + (size_t)(col0 + lrow)*KP + lseg*8;
    uint32_t dA = sbA + (lrow*SPITCH + lseg*8)*2;
    uint32_t dB = sbB + (lrow*SPITCH + lseg*8)*2;
    const int rstep = 64;

    // prologue: load ktiles 0,1,2 into stages 0,1,2
    #pragma unroll
    for (int p = 0; p < NSTAGE-1; p++) {
        size_t go = (size_t)p*32;
        uint32_t soff = p * STAGE_HALVES * 2;
        CP16(dA + soff,                  (const char*)(gA + go));
        CP16(dA + soff + rstep*SPITCH*2, (const char*)(gA + go + (size_t)rstep*KP));
        CP16(dB + soff,                  (const char*)(gB + go));
        CP16(dB + soff + rstep*SPITCH*2, (const char*)(gB + go + (size_t)rstep*KP));
        CP_COMMIT();
    }

    int aRow = warpM*32 + ((lane>>3)&1)*8 + (lane&7);
    int aCol = ((lane>>4)&1)*8;
    int bRow = warpN*64 + ((lane>>4)&1)*8 + (lane&7);
    int bCol = ((lane>>3)&1)*8;
    uint32_t aAddr0 = sbA + (aRow*SPITCH + aCol)*2;
    uint32_t bAddr0 = sbB + (bRow*SPITCH + bCol)*2;

    #pragma unroll
    for (int kt = 0; kt < NKT; kt++) {
        // wait until stage kt's loads complete
        if (kt <= NKT-3)      { CP_WAIT(2); }
        else if (kt == NKT-2) { CP_WAIT(1); }
        else                  { CP_WAIT(0); }
        __syncthreads();   // data visible to all; all warps done with stage (kt-1)%4

        if (kt + NSTAGE - 1 < NKT) {   // prefetch ktile kt+3 into stage (kt+3)%4 (= (kt-1)%4)
            size_t go = (size_t)(kt + NSTAGE - 1)*32;
            uint32_t soff = ((kt + NSTAGE - 1) & (NSTAGE-1)) * STAGE_HALVES * 2;
            CP16(dA + soff,                  (const char*)(gA + go));
            CP16(dA + soff + rstep*SPITCH*2, (const char*)(gA + go + (size_t)rstep*KP));
            CP16(dB + soff,                  (const char*)(gB + go));
            CP16(dB + soff + rstep*SPITCH*2, (const char*)(gB + go + (size_t)rstep*KP));
            CP_COMMIT();
        }

        uint32_t sa  = aAddr0 + (kt & (NSTAGE-1)) * STAGE_HALVES * 2;
        uint32_t sb2 = bAddr0 + (kt & (NSTAGE-1)) * STAGE_HALVES * 2;
        #pragma unroll
        for (int ks = 0; ks < 2; ks++) {
            uint32_t a[2][4];
            LDSM4(a[0][0],a[0][1],a[0][2],a[0][3], sa + ks*32);
            LDSM4(a[1][0],a[1][1],a[1][2],a[1][3], sa + ks*32 + 16*SPITCH*2);
            uint32_t b[8][2];
            #pragma unroll
            for (int ntp = 0; ntp < 4; ntp++) {
                uint32_t r0,r1,r2,r3;
                LDSM4(r0,r1,r2,r3, sb2 + ks*32 + ntp*16*SPITCH*2);
                b[ntp*2+0][0]=r0; b[ntp*2+0][1]=r1;
                b[ntp*2+1][0]=r2; b[ntp*2+1][1]=r3;
            }
            #pragma unroll
            for (int mt = 0; mt < 2; mt++)
                #pragma unroll
                for (int nt = 0; nt < 8; nt++)
                    MMA16816(c[mt][nt], a[mt], b[nt][0], b[nt][1]);
        }
        // no trailing sync: with 4 stages, the next overwrite targets a stage
        // all warps finished one full iteration ago (guarded by the kt-start sync)
    }

    int gr = lane >> 2, ci = lane & 3;
    #pragma unroll
    for (int mt = 0; mt < 2; mt++) {
        int r0w = row0 + warpM*32 + mt*16 + gr;
        #pragma unroll
        for (int nt = 0; nt < 8; nt++) {
            int col = col0 + warpN*64 + nt*8 + ci*2;
            if (colTile < 10) {
                if (r0w < NTOT)
                    *(__half2*)(g_xWh + (size_t)r0w*XWC + col) =
                        __floats2half2_rn(c[mt][nt][0], c[mt][nt][1]);
                if (r0w + 8 < NTOT)
                    *(__half2*)(g_xWh + (size_t)(r0w+8)*XWC + col) =
                        __floats2half2_rn(c[mt][nt][2], c[mt][nt][3]);
            } else {
                int h = col - XWC;
                float b0 = bias[h], b1 = bias[h+1];
                if (r0w < NTOT)
                    *(float2*)(out + (size_t)r0w*H + h) = make_float2(c[mt][nt][0] + b0, c[mt][nt][1] + b1);
                if (r0w + 8 < NTOT)
                    *(float2*)(out + (size_t)(r0w+8)*H + h) = make_float2(c[mt][nt][2] + b0, c[mt][nt][3] + b1);
            }
        }
    }
}

// ---------------- K5: dense per-graph edge GEMM ---------------------------
// agg[b] (96x256) = C[b] (96x464) @ xWflat[b] (464x256), 2 CTAs/graph (n halves)
#define CPITCH 472           /* C row pitch in halves */
#define BPITCH 136           /* B tile row pitch in halves (128 data + 8 pad) */
#define KTILES 29            /* ceil(450/16) */
#define BSTAGE (16*BPITCH*2) /* 4352 B per stage */
#define AGG_SMEM (96*CPITCH*2 + 2*BSTAGE)   /* 90624 + 8704 = 99328 */

__global__ void __launch_bounds__(256, 1) k_agg2(const int* __restrict__ edge_src,
                                                 const int* __restrict__ edge_dst,
                                                 const int* __restrict__ edge_type,
                                                 const float* __restrict__ node_att,
                                                 float* __restrict__ out) {
    extern __shared__ __half sm2[];
    __half* Cm = sm2;                          // [96][CPITCH]
    uint32_t sbC = smem_u32(Cm);
    uint32_t sbB = sbC + 96*CPITCH*2;          // 2 stages [16][BPITCH]
    int b = blockIdx.x >> 1, nh = blockIdx.x & 1;
    int tid = threadIdx.x, lane = tid & 31, w = tid >> 5;
    int n0 = nh * 128;

    // zero C (incl. padding cols)
    uint4 z = make_uint4(0,0,0,0);
    for (int i = tid; i < 96*CPITCH/8; i += 256) ((uint4*)Cm)[i] = z;
    __syncthreads();

    // scatter attention edges: C[dst][src*R+ty] += P[b][dst][src]
    #pragma unroll
    for (int q = 0; q < EA/256; q++) {
        int e = tid + q*256;
        int src = edge_src[(size_t)b*EA + e];
        int dst = edge_dst[(size_t)b*EA + e];
        int ty  = edge_type[(size_t)b*EA + e];
        float norm = g_P[((size_t)b*T + dst)*T + src];
        atomicAdd(&Cm[dst*CPITCH + src*R + ty], __float2half(norm));
    }
    // tag entries: C[T+o][src*R+(R-1)] = node_att[b][src][o]  (rows 90..94, unique)
    for (int q = tid; q < T*O; q += 256) {
        int src = q / O, o = q - src*O;
        Cm[(T+o)*CPITCH + src*R + (R-1)] = __float2half(node_att[((size_t)b*T + src)*O + o]);
    }

    // B tile loader
    int lrow = tid >> 4, lch = tid & 15;
    uint32_t dBs = sbB + lrow*(BPITCH*2) + lch*16;
    {
        int k = lrow;
        int src = k / R, ty = k - src*R;
        const __half* sp = g_xWh + ((size_t)(b*NPG + src)*XWC + ty*H + n0) + lch*8;
        CP16(dBs, (const char*)sp);
        CP_COMMIT();
    }

    float acc[6][2][4];
    #pragma unroll
    for (int mt = 0; mt < 6; mt++)
        #pragma unroll
        for (int nt = 0; nt < 2; nt++)
            #pragma unroll
            for (int q = 0; q < 4; q++) acc[mt][nt][q] = 0.f;

    uint32_t aAddr = sbC + ((((lane>>3)&1)*8 + (lane&7))*CPITCH + ((lane>>4)&1)*8)*2;
    uint32_t bAddr = (((lane>>3)&1)*8 + (lane&7))*(BPITCH*2) + (w*16 + ((lane>>4)&1)*8)*2;

    for (int kt = 0; kt < KTILES; kt++) {
        int s = kt & 1;
        if (kt + 1 < KTILES) {
            int k = (kt+1)*16 + lrow;
            int src = k / R, ty = k - src*R;
            const __half* sp = g_xWh + ((size_t)(b*NPG + src)*XWC + ty*H + n0) + lch*8;
            CP16(dBs + (s^1)*BSTAGE, (const char*)sp);
            CP_COMMIT();
            CP_WAIT(1);
        } else {
            CP_WAIT(0);
        }
        __syncthreads();

        uint32_t bb0, bb1, bb2, bb3;
        LDSM4T(bb0, bb1, bb2, bb3, sbB + s*BSTAGE + bAddr);
        #pragma unroll
        for (int mt = 0; mt < 6; mt++) {
            uint32_t a[4];
            LDSM4(a[0], a[1], a[2], a[3], aAddr + mt*16*CPITCH*2 + kt*32);
            MMA16816(acc[mt][0], a, bb0, bb1);
            MMA16816(acc[mt][1], a, bb2, bb3);
        }
        __syncthreads();
    }

    // epilogue: out[node] += acc  (each CTA owns its n-half exclusively)
    int gr = lane >> 2, ci = lane & 3;
    #pragma unroll
    for (int mt = 0; mt < 6; mt++) {
        #pragma unroll
        for (int hrow = 0; hrow < 2; hrow++) {
            int row = mt*16 + gr + hrow*8;
            if (row < NPG) {
                size_t node = (size_t)b*NPG + row;
                #pragma unroll
                for (int nt = 0; nt < 2; nt++) {
                    int col = n0 + w*16 + nt*8 + ci*2;
                    float2* p = (float2*)(out + node*H + col);
                    float2 v = *p;
                    v.x += acc[mt][nt][hrow*2 + 0];
                    v.y += acc[mt][nt][hrow*2 + 1];
                    *p = v;
                }
            }
        }
    }
}

// ---------------- launch (fork-join graph concurrency) --------------------
extern "C" void kernel_launch(void* const* d_in, const int* in_sizes, int n_in,
                              void* d_out, int out_size) {
    const float* M     = (const float*)d_in[0];
    const float* x     = (const float*)d_in[1];
    const float* natt  = (const float*)d_in[2];
    const float* Ws    = (const float*)d_in[3];
    const float* bases = (const float*)d_in[4];
    const float* comp  = (const float*)d_in[5];
    const float* root  = (const float*)d_in[6];
    const float* bias  = (const float*)d_in[7];
    const int* esrc    = (const int*)d_in[8];
    const int* edst    = (const int*)d_in[9];
    const int* etyp    = (const int*)d_in[10];
    float* out = (float*)d_out;

    static cudaStream_t s1 = nullptr, s2 = nullptr;
    static cudaEvent_t  ef = nullptr, e1 = nullptr, e2 = nullptr;
    static bool attr_done = false;
    if (!s1) {
        cudaStreamCreateWithFlags(&s1, cudaStreamNonBlocking);
        cudaStreamCreateWithFlags(&s2, cudaStreamNonBlocking);
        cudaEventCreateWithFlags(&ef, cudaEventDisableTiming);
        cudaEventCreateWithFlags(&e1, cudaEventDisableTiming);
        cudaEventCreateWithFlags(&e2, cudaEventDisableTiming);
    }
    if (!attr_done) {
        const int SMEM_ATTN = (2*96*257 + 90*91)*(int)sizeof(float);
        cudaFuncSetAttribute(k_attn, cudaFuncAttributeMaxDynamicSharedMemorySize, SMEM_ATTN);
        cudaFuncSetAttribute(k_agg2, cudaFuncAttributeMaxDynamicSharedMemorySize, AGG_SMEM);
        cudaFuncSetAttribute(k_mm,   cudaFuncAttributeMaxDynamicSharedMemorySize, MM_SMEM);
        attr_done = true;
    }
    const int SMEM_ATTN = (2*96*257 + 90*91)*(int)sizeof(float);

    // fork from capture-origin (default) stream
    cudaEventRecord(ef, 0);
    cudaStreamWaitEvent(s1, ef, 0);
    cudaStreamWaitEvent(s2, ef, 0);

    // branch A (default stream): buildB -> (join convA) -> mm
    k_buildB<<<(D*JW)/256, 256>>>(bases, comp, root);
    // branch B (s2): convA
    k_convA<<<(MROWS*256)/256, 256, 0, s2>>>(x);
    // branch C (s1): attn
    k_attn<<<BATCH, 256, SMEM_ATTN, s1>>>(M, Ws);

    // join convA into default stream before mm
    cudaEventRecord(e2, s2);
    cudaStreamWaitEvent(0, e2, 0);
    k_mm<<<dim3(MROWS/128, JW/128), 256, MM_SMEM>>>(bias, out);

    // join attn before agg2
    cudaEventRecord(e1, s1);
    cudaStreamWaitEvent(0, e1, 0);
    k_agg2<<<2*BATCH, 256, AGG_SMEM>>>(esrc, edst, etyp, natt, out);
}

// round 12
// speedup vs baseline: 2.5451x; 1.0027x over previous
#include <cuda_runtime.h>
#include <cuda_fp16.h>
#include <cstdint>
#include <cstddef>

#define BATCH 64
#define T 90
#define O 5
#define D 256
#define H 256
#define EA 4096
#define R 5
#define NB 8
#define NPG 95
#define NTOT (BATCH*NPG)      /* 6080 */
#define JW 1536               /* 5*256 relation cols + 256 root cols */
#define XWC 1280              /* relation part of xW */
#define MROWS 6144            /* NTOT padded to 48*128 */
#define KP 256                /* single fp16 term */

// ---------------- device scratch ----------------
__device__ __align__(128) __half g_xWh[(size_t)NTOT*XWC];         // 15.6 MB fp16
__device__ __align__(128) float g_P[(size_t)BATCH*T*T];           // softmax probs
__device__ __align__(128) __half g_Abf[(size_t)MROWS*KP];         // 3.1 MB  [row][k]
__device__ __align__(128) __half g_Bbf[(size_t)JW*KP];            // 0.8 MB  [n][k]

// ---------------- PTX helpers (baseline-PTX only: sm_80-class) ----------------
__device__ __forceinline__ uint32_t smem_u32(const void* p) {
    uint32_t a;
    asm("{ .reg .u64 t; cvta.to.shared.u64 t, %1; cvt.u32.u64 %0, t; }" : "=r"(a) : "l"(p));
    return a;
}
#define CP16(dst,src)    asm volatile("cp.async.cg.shared.global [%0], [%1], 16;"::"r"(dst),"l"(src):"memory")
#define CP_COMMIT()      asm volatile("cp.async.commit_group;":::"memory")
#define CP_WAIT(n)       asm volatile("cp.async.wait_group %0;"::"n"(n):"memory")
#define LDSM4(r0,r1,r2,r3,addr) \
    asm volatile("ldmatrix.sync.aligned.m8n8.x4.shared.b16 {%0,%1,%2,%3}, [%4];" \
                 : "=r"(r0),"=r"(r1),"=r"(r2),"=r"(r3) : "r"(addr))
#define LDSM4T(r0,r1,r2,r3,addr) \
    asm volatile("ldmatrix.sync.aligned.m8n8.x4.trans.shared.b16 {%0,%1,%2,%3}, [%4];" \
                 : "=r"(r0),"=r"(r1),"=r"(r2),"=r"(r3) : "r"(addr))
#define MMA16816(c, a, b0, b1) \
    asm volatile("mma.sync.aligned.m16n8k16.row.col.f32.f16.f16.f32 " \
                 "{%0,%1,%2,%3},{%4,%5,%6,%7},{%8,%9},{%0,%1,%2,%3};" \
                 : "+f"((c)[0]),"+f"((c)[1]),"+f"((c)[2]),"+f"((c)[3]) \
                 : "r"((a)[0]),"r"((a)[1]),"r"((a)[2]),"r"((a)[3]),"r"(b0),"r"(b1))

// ---------------- K1: prep = buildB + convA fused -------------------------
#define PREP_B_BLOCKS ((D*JW)/256)          /* 1536 */
#define PREP_A_BLOCKS ((MROWS*256)/256)     /* 6144 */
__global__ void k_prep(const float* __restrict__ bases,
                       const float* __restrict__ comp,
                       const float* __restrict__ root,
                       const float* __restrict__ x) {
    int bid = blockIdx.x, tid = threadIdx.x;
    if (bid < PREP_B_BLOCKS) {
        int idx = bid*256 + tid;            // 0 .. D*JW-1
        int d = idx / JW, j = idx - d*JW;
        float v;
        if (j < XWC) {
            int r = j >> 8, h = j & 255;
            float s = 0.f;
            #pragma unroll
            for (int n = 0; n < NB; n++)
                s += comp[r*NB + n] * bases[((size_t)n*D + d)*H + h];
            v = s;
        } else {
            v = root[d*H + (j - XWC)];
        }
        g_Bbf[(size_t)j*KP + d] = __float2half(v);
    } else {
        int idx = (bid - PREP_B_BLOCKS)*256 + tid;   // 0 .. MROWS*256-1
        int row = idx >> 8, col = idx & 255;
        float v = (row < NTOT) ? x[(size_t)row*D + col] : 0.f;
        g_Abf[(size_t)row*KP + col] = __float2half(v);
    }
}

// ---------------- K3: attention, 2 CTAs per graph (column halves) ---------
// CTA computes S[0:90, sh:sh+48] = M[b] @ Ws[sh:sh+48]^T, column softmax, write P
#define ATTN_SMEM ((96*257 + 48*257 + 90*49)*(int)sizeof(float))  /* 165672 */
__global__ void __launch_bounds__(128) k_attn(const float* __restrict__ M,
                                              const float* __restrict__ Ws) {
    extern __shared__ float sm[];
    float* sM = sm;                        // [96][257]
    float* sW = sm + 96*257;               // [48][257]
    float* sS = sm + 96*257 + 48*257;      // [90][49]
    int b = blockIdx.x >> 1;
    int sh = (blockIdx.x & 1) * 48;
    int tid = threadIdx.x;                 // 128 threads

    for (int q = tid; q < T*(D/4); q += 128) {
        int m = q >> 6, d4 = (q & 63) << 2;
        float4 v = *(const float4*)(M + ((size_t)b*T + m)*D + d4);
        float* p = sM + m*257 + d4;
        p[0]=v.x; p[1]=v.y; p[2]=v.z; p[3]=v.w;
    }
    for (int q = tid; q < 6*257; q += 128) sM[90*257 + q] = 0.f;
    for (int q = tid; q < 48*(D/4); q += 128) {
        int r = q >> 6, d4 = (q & 63) << 2;
        int s = sh + r;
        float4 v = make_float4(0.f,0.f,0.f,0.f);
        if (s < T) v = *(const float4*)(Ws + (size_t)s*D + d4);
        float* p = sW + r*257 + d4;
        p[0]=v.x; p[1]=v.y; p[2]=v.z; p[3]=v.w;
    }
    __syncthreads();

    int tx = tid & 7, ty = tid >> 3;       // 8 x 16
    int m0 = ty*6, s0 = tx*6;              // 96 rows, 48 cols
    float acc[6][6];
    #pragma unroll
    for (int i = 0; i < 6; i++)
        #pragma unroll
        for (int j = 0; j < 6; j++) acc[i][j] = 0.f;
    for (int k = 0; k < D; k++) {
        float a[6], bb[6];
        #pragma unroll
        for (int i = 0; i < 6; i++) { a[i] = sM[(m0+i)*257 + k]; bb[i] = sW[(s0+i)*257 + k]; }
        #pragma unroll
        for (int i = 0; i < 6; i++)
            #pragma unroll
            for (int j = 0; j < 6; j++) acc[i][j] += a[i]*bb[j];
    }
    #pragma unroll
    for (int i = 0; i < 6; i++)
        #pragma unroll
        for (int j = 0; j < 6; j++) {
            int m = m0+i, sl = s0+j;
            if (m < T && sh + sl < T) sS[m*49 + sl] = acc[i][j];
        }
    __syncthreads();

    if (tid < 48 && sh + tid < T) {
        int sl = tid, sg = sh + tid;
        float mx = -1e30f;
        for (int t = 0; t < T; t++) mx = fmaxf(mx, sS[t*49 + sl]);
        float den = 0.f;
        for (int t = 0; t < T; t++) den += __expf(sS[t*49 + sl] - mx);
        float inv = 1.f/den;
        for (int t = 0; t < T; t++)
            g_P[((size_t)b*T + t)*T + sg] = __expf(sS[t*49 + sl] - mx) * inv;
    }
}

// ---------------- K2: mma.sync fp16 GEMM, 4-stage pipeline ----------------
#define SPITCH 40
#define STAGE_HALVES (128*SPITCH)
#define NKT (KP/32)          /* 8 */
#define NSTAGE 4
#define MM_SMEM (2*NSTAGE*STAGE_HALVES*2)   /* 81920 B */

__global__ void __launch_bounds__(256, 2) k_mm(const float* __restrict__ bias,
                                               float* __restrict__ out) {
    extern __shared__ __half smm[];
    uint32_t sbA = smem_u32(smm);
    uint32_t sbB = sbA + NSTAGE*STAGE_HALVES*2;
    int tid = threadIdx.x, lane = tid & 31, wid = tid >> 5;
    int warpM = wid & 3, warpN = wid >> 2;
    int row0 = blockIdx.x * 128;
    int colTile = blockIdx.y, col0 = colTile * 128;

    float c[2][8][4];
    #pragma unroll
    for (int mt = 0; mt < 2; mt++)
        #pragma unroll
        for (int nt = 0; nt < 8; nt++)
            #pragma unroll
            for (int q = 0; q < 4; q++) c[mt][nt][q] = 0.f;

    int lrow = tid >> 2, lseg = tid & 3;
    const __half* gA = g_Abf + (size_t)(row0 + lrow)*KP + lseg*8;
    const __half* gB = g_Bbf + (size_t)(col0 + lrow)*KP + lseg*8;
    uint32_t dA = sbA + (lrow*SPITCH + lseg*8)*2;
    uint32_t dB = sbB + (lrow*SPITCH + lseg*8)*2;
    const int rstep = 64;

    #pragma unroll
    for (int p = 0; p < NSTAGE-1; p++) {
        size_t go = (size_t)p*32;
        uint32_t soff = p * STAGE_HALVES * 2;
        CP16(dA + soff,                  (const char*)(gA + go));
        CP16(dA + soff + rstep*SPITCH*2, (const char*)(gA + go + (size_t)rstep*KP));
        CP16(dB + soff,                  (const char*)(gB + go));
        CP16(dB + soff + rstep*SPITCH*2, (const char*)(gB + go + (size_t)rstep*KP));
        CP_COMMIT();
    }

    int aRow = warpM*32 + ((lane>>3)&1)*8 + (lane&7);
    int aCol = ((lane>>4)&1)*8;
    int bRow = warpN*64 + ((lane>>4)&1)*8 + (lane&7);
    int bCol = ((lane>>3)&1)*8;
    uint32_t aAddr0 = sbA + (aRow*SPITCH + aCol)*2;
    uint32_t bAddr0 = sbB + (bRow*SPITCH + bCol)*2;

    #pragma unroll
    for (int kt = 0; kt < NKT; kt++) {
        if (kt <= NKT-3)      { CP_WAIT(2); }
        else if (kt == NKT-2) { CP_WAIT(1); }
        else                  { CP_WAIT(0); }
        __syncthreads();

        if (kt + NSTAGE - 1 < NKT) {
            size_t go = (size_t)(kt + NSTAGE - 1)*32;
            uint32_t soff = ((kt + NSTAGE - 1) & (NSTAGE-1)) * STAGE_HALVES * 2;
            CP16(dA + soff,                  (const char*)(gA + go));
            CP16(dA + soff + rstep*SPITCH*2, (const char*)(gA + go + (size_t)rstep*KP));
            CP16(dB + soff,                  (const char*)(gB + go));
            CP16(dB + soff + rstep*SPITCH*2, (const char*)(gB + go + (size_t)rstep*KP));
            CP_COMMIT();
        }

        uint32_t sa  = aAddr0 + (kt & (NSTAGE-1)) * STAGE_HALVES * 2;
        uint32_t sb2 = bAddr0 + (kt & (NSTAGE-1)) * STAGE_HALVES * 2;
        #pragma unroll
        for (int ks = 0; ks < 2; ks++) {
            uint32_t a[2][4];
            LDSM4(a[0][0],a[0][1],a[0][2],a[0][3], sa + ks*32);
            LDSM4(a[1][0],a[1][1],a[1][2],a[1][3], sa + ks*32 + 16*SPITCH*2);
            uint32_t b[8][2];
            #pragma unroll
            for (int ntp = 0; ntp < 4; ntp++) {
                uint32_t r0,r1,r2,r3;
                LDSM4(r0,r1,r2,r3, sb2 + ks*32 + ntp*16*SPITCH*2);
                b[ntp*2+0][0]=r0; b[ntp*2+0][1]=r1;
                b[ntp*2+1][0]=r2; b[ntp*2+1][1]=r3;
            }
            #pragma unroll
            for (int mt = 0; mt < 2; mt++)
                #pragma unroll
                for (int nt = 0; nt < 8; nt++)
                    MMA16816(c[mt][nt], a[mt], b[nt][0], b[nt][1]);
        }
    }

    int gr = lane >> 2, ci = lane & 3;
    #pragma unroll
    for (int mt = 0; mt < 2; mt++) {
        int r0w = row0 + warpM*32 + mt*16 + gr;
        #pragma unroll
        for (int nt = 0; nt < 8; nt++) {
            int col = col0 + warpN*64 + nt*8 + ci*2;
            if (colTile < 10) {
                if (r0w < NTOT)
                    *(__half2*)(g_xWh + (size_t)r0w*XWC + col) =
                        __floats2half2_rn(c[mt][nt][0], c[mt][nt][1]);
                if (r0w + 8 < NTOT)
                    *(__half2*)(g_xWh + (size_t)(r0w+8)*XWC + col) =
                        __floats2half2_rn(c[mt][nt][2], c[mt][nt][3]);
            } else {
                int h = col - XWC;
                float b0 = bias[h], b1 = bias[h+1];
                if (r0w < NTOT)
                    *(float2*)(out + (size_t)r0w*H + h) = make_float2(c[mt][nt][0] + b0, c[mt][nt][1] + b1);
                if (r0w + 8 < NTOT)
                    *(float2*)(out + (size_t)(r0w+8)*H + h) = make_float2(c[mt][nt][2] + b0, c[mt][nt][3] + b1);
            }
        }
    }
}

// ---------------- K5: dense per-graph edge GEMM ---------------------------
#define CPITCH 472
#define BPITCH 136
#define KTILES 29
#define BSTAGE (16*BPITCH*2)
#define AGG_SMEM (96*CPITCH*2 + 2*BSTAGE)   /* 99328 */

__global__ void __launch_bounds__(256, 1) k_agg2(const int* __restrict__ edge_src,
                                                 const int* __restrict__ edge_dst,
                                                 const int* __restrict__ edge_type,
                                                 const float* __restrict__ node_att,
                                                 float* __restrict__ out) {
    extern __shared__ __half sm2[];
    __half* Cm = sm2;
    uint32_t sbC = smem_u32(Cm);
    uint32_t sbB = sbC + 96*CPITCH*2;
    int b = blockIdx.x >> 1, nh = blockIdx.x & 1;
    int tid = threadIdx.x, lane = tid & 31, w = tid >> 5;
    int n0 = nh * 128;

    uint4 z = make_uint4(0,0,0,0);
    for (int i = tid; i < 96*CPITCH/8; i += 256) ((uint4*)Cm)[i] = z;
    __syncthreads();

    #pragma unroll
    for (int q = 0; q < EA/256; q++) {
        int e = tid + q*256;
        int src = edge_src[(size_t)b*EA + e];
        int dst = edge_dst[(size_t)b*EA + e];
        int ty  = edge_type[(size_t)b*EA + e];
        float norm = g_P[((size_t)b*T + dst)*T + src];
        atomicAdd(&Cm[dst*CPITCH + src*R + ty], __float2half(norm));
    }
    for (int q = tid; q < T*O; q += 256) {
        int src = q / O, o = q - src*O;
        Cm[(T+o)*CPITCH + src*R + (R-1)] = __float2half(node_att[((size_t)b*T + src)*O + o]);
    }

    int lrow = tid >> 4, lch = tid & 15;
    uint32_t dBs = sbB + lrow*(BPITCH*2) + lch*16;
    {
        int k = lrow;
        int src = k / R, ty = k - src*R;
        const __half* sp = g_xWh + ((size_t)(b*NPG + src)*XWC + ty*H + n0) + lch*8;
        CP16(dBs, (const char*)sp);
        CP_COMMIT();
    }

    float acc[6][2][4];
    #pragma unroll
    for (int mt = 0; mt < 6; mt++)
        #pragma unroll
        for (int nt = 0; nt < 2; nt++)
            #pragma unroll
            for (int q = 0; q < 4; q++) acc[mt][nt][q] = 0.f;

    uint32_t aAddr = sbC + ((((lane>>3)&1)*8 + (lane&7))*CPITCH + ((lane>>4)&1)*8)*2;
    uint32_t bAddr = (((lane>>3)&1)*8 + (lane&7))*(BPITCH*2) + (w*16 + ((lane>>4)&1)*8)*2;

    for (int kt = 0; kt < KTILES; kt++) {
        int s = kt & 1;
        if (kt + 1 < KTILES) {
            int k = (kt+1)*16 + lrow;
            int src = k / R, ty = k - src*R;
            const __half* sp = g_xWh + ((size_t)(b*NPG + src)*XWC + ty*H + n0) + lch*8;
            CP16(dBs + (s^1)*BSTAGE, (const char*)sp);
            CP_COMMIT();
            CP_WAIT(1);
        } else {
            CP_WAIT(0);
        }
        __syncthreads();

        uint32_t bb0, bb1, bb2, bb3;
        LDSM4T(bb0, bb1, bb2, bb3, sbB + s*BSTAGE + bAddr);
        #pragma unroll
        for (int mt = 0; mt < 6; mt++) {
            uint32_t a[4];
            LDSM4(a[0], a[1], a[2], a[3], aAddr + mt*16*CPITCH*2 + kt*32);
            MMA16816(acc[mt][0], a, bb0, bb1);
            MMA16816(acc[mt][1], a, bb2, bb3);
        }
        __syncthreads();
    }

    int gr = lane >> 2, ci = lane & 3;
    #pragma unroll
    for (int mt = 0; mt < 6; mt++) {
        #pragma unroll
        for (int hrow = 0; hrow < 2; hrow++) {
            int row = mt*16 + gr + hrow*8;
            if (row < NPG) {
                size_t node = (size_t)b*NPG + row;
                #pragma unroll
                for (int nt = 0; nt < 2; nt++) {
                    int col = n0 + w*16 + nt*8 + ci*2;
                    float2* p = (float2*)(out + node*H + col);
                    float2 v = *p;
                    v.x += acc[mt][nt][hrow*2 + 0];
                    v.y += acc[mt][nt][hrow*2 + 1];
                    *p = v;
                }
            }
        }
    }
}

// ---------------- launch (fork-join graph concurrency) --------------------
extern "C" void kernel_launch(void* const* d_in, const int* in_sizes, int n_in,
                              void* d_out, int out_size) {
    const float* M     = (const float*)d_in[0];
    const float* x     = (const float*)d_in[1];
    const float* natt  = (const float*)d_in[2];
    const float* Ws    = (const float*)d_in[3];
    const float* bases = (const float*)d_in[4];
    const float* comp  = (const float*)d_in[5];
    const float* root  = (const float*)d_in[6];
    const float* bias  = (const float*)d_in[7];
    const int* esrc    = (const int*)d_in[8];
    const int* edst    = (const int*)d_in[9];
    const int* etyp    = (const int*)d_in[10];
    float* out = (float*)d_out;

    static cudaStream_t s1 = nullptr;
    static cudaEvent_t  ef = nullptr, e1 = nullptr;
    static bool attr_done = false;
    if (!s1) {
        cudaStreamCreateWithFlags(&s1, cudaStreamNonBlocking);
        cudaEventCreateWithFlags(&ef, cudaEventDisableTiming);
        cudaEventCreateWithFlags(&e1, cudaEventDisableTiming);
    }
    if (!attr_done) {
        cudaFuncSetAttribute(k_attn, cudaFuncAttributeMaxDynamicSharedMemorySize, ATTN_SMEM);
        cudaFuncSetAttribute(k_agg2, cudaFuncAttributeMaxDynamicSharedMemorySize, AGG_SMEM);
        cudaFuncSetAttribute(k_mm,   cudaFuncAttributeMaxDynamicSharedMemorySize, MM_SMEM);
        attr_done = true;
    }

    // fork attn onto s1
    cudaEventRecord(ef, 0);
    cudaStreamWaitEvent(s1, ef, 0);
    k_attn<<<2*BATCH, 128, ATTN_SMEM, s1>>>(M, Ws);

    // main chain: prep -> mm
    k_prep<<<PREP_B_BLOCKS + PREP_A_BLOCKS, 256>>>(bases, comp, root, x);
    k_mm<<<dim3(MROWS/128, JW/128), 256, MM_SMEM>>>(bias, out);

    // join attn before agg2
    cudaEventRecord(e1, s1);
    cudaStreamWaitEvent(0, e1, 0);
    k_agg2<<<2*BATCH, 256, AGG_SMEM>>>(esrc, edst, etyp, natt, out);
}